// round 4
// baseline (speedup 1.0000x reference)
#include <cuda_runtime.h>
#include <stdint.h>

#define N_NODES 50000
#define N_EDGES 500000
#define NPG     6250
#define N_GRAPHS 8
#define TOT_EDGES (N_EDGES + N_NODES)
#define NC 10

// ---------------- scratch (static __device__, no allocation) ----------------
__device__ float g_xp1[(size_t)N_NODES * 256];   // layer1 projected features [N,2,128]
__device__ float g_h1 [(size_t)N_NODES * 128];   // layer1 output (post relu)
__device__ float g_xp2[(size_t)N_NODES * 128];   // layer2 projected features [N,2,64]
__device__ float g_h2 [(size_t)N_NODES * 64];    // layer2 output
__device__ float g_als[N_NODES * 2];
__device__ float g_ald[N_NODES * 2];
__device__ int   g_rowptr[N_NODES + 1];
__device__ int   g_cursor[N_NODES];
__device__ int   g_col[TOT_EDGES];
__device__ float g_eav[TOT_EDGES];
__device__ float g_gsum[N_GRAPHS];
__device__ int   g_gcnt[N_GRAPHS];
__device__ float g_mean[N_GRAPHS];
__device__ float g_ke[4];   // ke1[0],ke1[1],ke2[0],ke2[1]

// ---------------- init: deg=1 (self loop), zero graph stats ----------------
__global__ void k_init() {
    int i = blockIdx.x * blockDim.x + threadIdx.x;
    if (i < N_NODES) g_cursor[i] = 1;
    if (i < N_GRAPHS) { g_gsum[i] = 0.f; g_gcnt[i] = 0; }
}

// ---------------- pass over edges: per-graph attr stats + in-degree hist ----
__global__ void k_edge_pass1(const int* __restrict__ src, const int* __restrict__ dst,
                             const float* __restrict__ ea) {
    __shared__ float ss[N_GRAPHS];
    __shared__ int   sc[N_GRAPHS];
    if (threadIdx.x < N_GRAPHS) { ss[threadIdx.x] = 0.f; sc[threadIdx.x] = 0; }
    __syncthreads();
    for (int e = blockIdx.x * blockDim.x + threadIdx.x; e < N_EDGES;
         e += gridDim.x * blockDim.x) {
        int s = src[e];
        int d = dst[e];
        int g = s / NPG;
        atomicAdd(&ss[g], ea[e]);
        atomicAdd(&sc[g], 1);
        atomicAdd(&g_cursor[d], 1);
    }
    __syncthreads();
    if (threadIdx.x < N_GRAPHS) {
        atomicAdd(&g_gsum[threadIdx.x], ss[threadIdx.x]);
        atomicAdd(&g_gcnt[threadIdx.x], sc[threadIdx.x]);
    }
}

// ---------------- tiny: per-graph means + edge-attention scalars ke --------
__global__ void k_finalize(const float* __restrict__ We1, const float* __restrict__ ae1,
                           const float* __restrict__ We2, const float* __restrict__ ae2) {
    int t = threadIdx.x, w = t >> 5, lane = t & 31;
    float v = 0.f;
    if (w == 0)      { for (int c = lane; c < 128; c += 32) v += We1[c]       * ae1[c]; }
    else if (w == 1) { for (int c = lane; c < 128; c += 32) v += We1[128 + c] * ae1[128 + c]; }
    else if (w == 2) { for (int c = lane; c <  64; c += 32) v += We2[c]       * ae2[c]; }
    else if (w == 3) { for (int c = lane; c <  64; c += 32) v += We2[64 + c]  * ae2[64 + c]; }
    #pragma unroll
    for (int off = 16; off; off >>= 1) v += __shfl_xor_sync(0xffffffffu, v, off);
    if (w < 4 && lane == 0) g_ke[w] = v;
    if (w == 4 && lane < N_GRAPHS)
        g_mean[lane] = g_gsum[lane] / (float)g_gcnt[lane];
}

// ---------------- single-block exclusive scan: deg -> rowptr, cursor -------
__global__ void k_scan() {
    __shared__ int sums[1024];
    const int CH = 49;                 // 1024*49 >= 50000
    int t = threadIdx.x;
    int start = t * CH, end = min(start + CH, N_NODES);
    int s = 0;
    for (int j = start; j < end; j++) s += g_cursor[j];
    sums[t] = s;
    __syncthreads();
    for (int off = 1; off < 1024; off <<= 1) {
        int v = 0;
        if (t >= off) v = sums[t - off];
        __syncthreads();
        if (t >= off) sums[t] += v;
        __syncthreads();
    }
    int run = (t == 0) ? 0 : sums[t - 1];
    for (int j = start; j < end; j++) {
        int d = g_cursor[j];
        g_rowptr[j] = run;
        g_cursor[j] = run;
        run += d;
    }
    if (t == 0) g_rowptr[N_NODES] = sums[1023];
}

// ---------------- CSR fill (real edges + self loops) ------------------------
__global__ void k_fill(const int* __restrict__ src, const int* __restrict__ dst,
                       const float* __restrict__ ea) {
    for (int i = blockIdx.x * blockDim.x + threadIdx.x; i < TOT_EDGES;
         i += gridDim.x * blockDim.x) {
        if (i < N_EDGES) {
            int d = dst[i];
            int p = atomicAdd(&g_cursor[d], 1);
            g_col[p] = src[i];
            g_eav[p] = ea[i];
        } else {
            int n = i - N_EDGES;
            int p = atomicAdd(&g_cursor[n], 1);
            g_col[p] = n;
            g_eav[p] = g_mean[n / NPG];
        }
    }
}

// ---------------- SGEMM: C[M,N] = A[M,K] @ B[K,N] (row major) --------------
// 128x128 tile, BK=8, 8x8 per thread, 256 threads.
__global__ void __launch_bounds__(256) k_sgemm(const float* __restrict__ A,
                                               const float* __restrict__ B,
                                               float* __restrict__ C,
                                               int M, int Nn, int K) {
    __shared__ float As[8][132];   // transposed, padded
    __shared__ float Bs[8][128];
    int tid  = threadIdx.x;
    int brow = blockIdx.y * 128, bcol = blockIdx.x * 128;
    int ar = tid >> 1, ac = (tid & 1) * 4;          // A: row, k-offset
    int br = tid >> 5, bc4 = (tid & 31) * 4;        // B: k-row, col offset
    int ty = (tid >> 4) * 8, tn = (tid & 15) * 8;   // thread tile origin
    float acc[8][8];
    #pragma unroll
    for (int i = 0; i < 8; i++)
        #pragma unroll
        for (int j = 0; j < 8; j++) acc[i][j] = 0.f;

    for (int k0 = 0; k0 < K; k0 += 8) {
        float4 av = make_float4(0.f, 0.f, 0.f, 0.f);
        int arow = brow + ar;
        if (arow < M)
            av = *reinterpret_cast<const float4*>(&A[(size_t)arow * K + k0 + ac]);
        As[ac + 0][ar] = av.x; As[ac + 1][ar] = av.y;
        As[ac + 2][ar] = av.z; As[ac + 3][ar] = av.w;
        float4 bv = *reinterpret_cast<const float4*>(&B[(size_t)(k0 + br) * Nn + bcol + bc4]);
        *reinterpret_cast<float4*>(&Bs[br][bc4]) = bv;
        __syncthreads();
        #pragma unroll
        for (int k = 0; k < 8; k++) {
            float a[8], b[8];
            *(float4*)&a[0] = *(float4*)&As[k][ty];
            *(float4*)&a[4] = *(float4*)&As[k][ty + 4];
            *(float4*)&b[0] = *(float4*)&Bs[k][tn];
            *(float4*)&b[4] = *(float4*)&Bs[k][tn + 4];
            #pragma unroll
            for (int i = 0; i < 8; i++)
                #pragma unroll
                for (int j = 0; j < 8; j++) acc[i][j] += a[i] * b[j];
        }
        __syncthreads();
    }
    #pragma unroll
    for (int i = 0; i < 8; i++) {
        int row = brow + ty + i;
        if (row < M) {
            *(float4*)&C[(size_t)row * Nn + bcol + tn]     =
                make_float4(acc[i][0], acc[i][1], acc[i][2], acc[i][3]);
            *(float4*)&C[(size_t)row * Nn + bcol + tn + 4] =
                make_float4(acc[i][4], acc[i][5], acc[i][6], acc[i][7]);
        }
    }
}

// ---------------- per-node attention logits: al_s, al_d --------------------
template <int C>
__global__ void k_alpha(const float* __restrict__ xp, const float* __restrict__ asrc,
                        const float* __restrict__ adst) {
    int warp = (blockIdx.x * blockDim.x + threadIdx.x) >> 5;
    int lane = threadIdx.x & 31;
    if (warp >= N_NODES) return;
    const float* row = xp + (size_t)warp * 2 * C;
    float s0 = 0.f, d0 = 0.f, s1 = 0.f, d1 = 0.f;
    #pragma unroll
    for (int j = 0; j < C / 32; j++) {
        int c = lane + 32 * j;
        float v0 = row[c], v1 = row[C + c];
        s0 += v0 * asrc[c];      d0 += v0 * adst[c];
        s1 += v1 * asrc[C + c];  d1 += v1 * adst[C + c];
    }
    #pragma unroll
    for (int off = 16; off; off >>= 1) {
        s0 += __shfl_xor_sync(0xffffffffu, s0, off);
        d0 += __shfl_xor_sync(0xffffffffu, d0, off);
        s1 += __shfl_xor_sync(0xffffffffu, s1, off);
        d1 += __shfl_xor_sync(0xffffffffu, d1, off);
    }
    if (lane == 0) {
        g_als[2 * warp]     = s0;  g_als[2 * warp + 1] = s1;
        g_ald[2 * warp]     = d0;  g_ald[2 * warp + 1] = d1;
    }
}

// ---------------- warp-per-dst online-softmax aggregation ------------------
template <int C, bool RELU>
__global__ void k_agg(const float* __restrict__ xp, const float* __restrict__ bias,
                      float* __restrict__ out, int keoff) {
    int warp = (blockIdx.x * blockDim.x + threadIdx.x) >> 5;
    int lane = threadIdx.x & 31;
    if (warp >= N_NODES) return;
    const int J = C / 32;
    float acc0[J], acc1[J];
    #pragma unroll
    for (int j = 0; j < J; j++) { acc0[j] = 0.f; acc1[j] = 0.f; }
    float m0 = -1e30f, m1 = -1e30f, d0 = 0.f, d1 = 0.f;
    float ad0 = g_ald[2 * warp], ad1 = g_ald[2 * warp + 1];
    float ke0 = g_ke[keoff], ke1 = g_ke[keoff + 1];
    int p0 = g_rowptr[warp], p1 = g_rowptr[warp + 1];
    for (int p = p0; p < p1; p++) {
        int s = g_col[p];
        float ea = g_eav[p];
        float a0 = g_als[2 * s]     + ad0 + ea * ke0;
        float a1 = g_als[2 * s + 1] + ad1 + ea * ke1;
        a0 = a0 > 0.f ? a0 : 0.2f * a0;
        a1 = a1 > 0.f ? a1 : 0.2f * a1;
        float nm0 = fmaxf(m0, a0), nm1 = fmaxf(m1, a1);
        float sc0 = __expf(m0 - nm0), sc1 = __expf(m1 - nm1);
        float w0  = __expf(a0 - nm0), w1  = __expf(a1 - nm1);
        d0 = d0 * sc0 + w0;  d1 = d1 * sc1 + w1;
        m0 = nm0;  m1 = nm1;
        const float* row = xp + (size_t)s * 2 * C;
        #pragma unroll
        for (int j = 0; j < J; j++) {
            acc0[j] = acc0[j] * sc0 + w0 * row[lane + 32 * j];
            acc1[j] = acc1[j] * sc1 + w1 * row[C + lane + 32 * j];
        }
    }
    float r0 = 1.f / (d0 + 1e-16f), r1 = 1.f / (d1 + 1e-16f);
    #pragma unroll
    for (int j = 0; j < J; j++) {
        int c = lane + 32 * j;
        float v = 0.5f * (acc0[j] * r0 + acc1[j] * r1) + bias[c];
        if (RELU) v = fmaxf(v, 0.f);
        out[(size_t)warp * C + c] = v;
    }
}

// ---------------- classifier: pred = h2 @ Wc + bc --------------------------
__global__ void __launch_bounds__(256) k_cls(const float* __restrict__ Wc,
                                             const float* __restrict__ bc,
                                             float* __restrict__ out) {
    __shared__ float sh[64][65];
    __shared__ float swc[64 * NC];
    __shared__ float sbc[NC];
    int tid = threadIdx.x;
    int n0 = blockIdx.x * 64;
    for (int i = tid; i < 64 * NC; i += 256) swc[i] = Wc[i];
    if (tid < NC) sbc[tid] = bc[tid];
    for (int i = tid; i < 64 * 64; i += 256) {
        int r = i >> 6, k = i & 63;
        int n = n0 + r;
        sh[r][k] = (n < N_NODES) ? g_h2[(size_t)n * 64 + k] : 0.f;
    }
    __syncthreads();
    for (int idx = tid; idx < 64 * NC; idx += 256) {
        int r = idx / NC, c = idx % NC;
        int n = n0 + r;
        if (n < N_NODES) {
            float s = sbc[c];
            #pragma unroll
            for (int k = 0; k < 64; k++) s += sh[r][k] * swc[k * NC + c];
            out[(size_t)n * NC + c] = s;
        }
    }
}

__global__ void k_y(const int* __restrict__ y, float* __restrict__ out) {
    int i = blockIdx.x * blockDim.x + threadIdx.x;
    if (i < N_NODES) out[i] = (float)y[i];
}

// ---------------- launch ----------------------------------------------------
static void* sym(const void* s) { void* p = nullptr; cudaGetSymbolAddress(&p, s); return p; }

extern "C" void kernel_launch(void* const* d_in, const int* in_sizes, int n_in,
                              void* d_out, int out_size) {
    const float* x    = (const float*)d_in[0];
    const int*   ei   = (const int*)  d_in[1];
    const float* ea   = (const float*)d_in[2];
    const int*   y    = (const int*)  d_in[4];
    const float* W1   = (const float*)d_in[5];
    const float* as1  = (const float*)d_in[6];
    const float* ad1  = (const float*)d_in[7];
    const float* We1  = (const float*)d_in[8];
    const float* ae1  = (const float*)d_in[9];
    const float* b1   = (const float*)d_in[10];
    const float* W2   = (const float*)d_in[11];
    const float* as2  = (const float*)d_in[12];
    const float* ad2  = (const float*)d_in[13];
    const float* We2  = (const float*)d_in[14];
    const float* ae2  = (const float*)d_in[15];
    const float* b2   = (const float*)d_in[16];
    const float* Wc   = (const float*)d_in[17];
    const float* bc   = (const float*)d_in[18];
    float* out = (float*)d_out;
    const int* src = ei;
    const int* dst = ei + N_EDGES;

    float* xp1 = (float*)sym(g_xp1);
    float* h1  = (float*)sym(g_h1);
    float* xp2 = (float*)sym(g_xp2);

    k_init<<<(N_NODES + 255) / 256, 256>>>();
    k_edge_pass1<<<512, 256>>>(src, dst, ea);
    k_finalize<<<1, 160>>>(We1, ae1, We2, ae2);
    k_scan<<<1, 1024>>>();
    k_fill<<<1024, 256>>>(src, dst, ea);

    // Layer 1
    { dim3 g(2, (N_NODES + 127) / 128); k_sgemm<<<g, 256>>>(x, W1, xp1, N_NODES, 256, 256); }
    k_alpha<128><<<(N_NODES * 32 + 255) / 256, 256>>>(xp1, as1, ad1);
    k_agg<128, true><<<(N_NODES * 32 + 255) / 256, 256>>>(xp1, b1, h1, 0);

    // Layer 2
    { dim3 g(1, (N_NODES + 127) / 128); k_sgemm<<<g, 256>>>(h1, W2, xp2, N_NODES, 128, 128); }
    k_alpha<64><<<(N_NODES * 32 + 255) / 256, 256>>>(xp2, as2, ad2);
    k_agg<64, false><<<(N_NODES * 32 + 255) / 256, 256>>>(xp2, b2, (float*)sym(g_h2), 2);

    // Classifier + y
    k_cls<<<(N_NODES + 63) / 64, 256>>>(Wc, bc, out);
    if (out_size >= N_NODES * NC + N_NODES)
        k_y<<<(N_NODES + 255) / 256, 256>>>(y, out + (size_t)N_NODES * NC);
}

// round 5
// speedup vs baseline: 1.2209x; 1.2209x over previous
#include <cuda_runtime.h>
#include <stdint.h>

#define N_NODES 50000
#define N_EDGES 500000
#define NPG     6250
#define N_GRAPHS 8
#define TOT_EDGES (N_EDGES + N_NODES)
#define NC 10
#define NBLK_SCAN ((N_NODES + 255) / 256)   // 196

// ---------------- scratch (static __device__, no allocation) ----------------
__device__ __align__(16) float g_xp1[(size_t)N_NODES * 256];
__device__ __align__(16) float g_h1 [(size_t)N_NODES * 128];
__device__ __align__(16) float g_xp2[(size_t)N_NODES * 128];
__device__ __align__(16) float g_h2 [(size_t)N_NODES * 64];
__device__ float g_als[N_NODES * 2];
__device__ float g_ald[N_NODES * 2];
__device__ int   g_rowptr[N_NODES + 1];
__device__ int   g_cursor[N_NODES];
__device__ int   g_col[TOT_EDGES];
__device__ float g_eav[TOT_EDGES];
__device__ float g_gsum[N_GRAPHS];
__device__ int   g_gcnt[N_GRAPHS];
__device__ float g_mean[N_GRAPHS];
__device__ float g_ke[4];   // ke1[0],ke1[1],ke2[0],ke2[1]
__device__ int   g_bsum[NBLK_SCAN];

// ---------------- init: deg=1 (self loop), zero graph stats ----------------
__global__ void k_init() {
    int i = blockIdx.x * blockDim.x + threadIdx.x;
    if (i < N_NODES) g_cursor[i] = 1;
    if (i < N_GRAPHS) { g_gsum[i] = 0.f; g_gcnt[i] = 0; }
}

// ---------------- pass over edges: per-graph attr stats + in-degree hist ----
__global__ void k_edge_pass1(const int* __restrict__ src, const int* __restrict__ dst,
                             const float* __restrict__ ea) {
    __shared__ float ss[N_GRAPHS];
    __shared__ int   sc[N_GRAPHS];
    if (threadIdx.x < N_GRAPHS) { ss[threadIdx.x] = 0.f; sc[threadIdx.x] = 0; }
    __syncthreads();
    for (int e = blockIdx.x * blockDim.x + threadIdx.x; e < N_EDGES;
         e += gridDim.x * blockDim.x) {
        int s = src[e];
        int d = dst[e];
        int g = s / NPG;
        atomicAdd(&ss[g], ea[e]);
        atomicAdd(&sc[g], 1);
        atomicAdd(&g_cursor[d], 1);
    }
    __syncthreads();
    if (threadIdx.x < N_GRAPHS) {
        atomicAdd(&g_gsum[threadIdx.x], ss[threadIdx.x]);
        atomicAdd(&g_gcnt[threadIdx.x], sc[threadIdx.x]);
    }
}

// ---------------- tiny: per-graph means + edge-attention scalars ke --------
__global__ void k_finalize(const float* __restrict__ We1, const float* __restrict__ ae1,
                           const float* __restrict__ We2, const float* __restrict__ ae2) {
    int t = threadIdx.x, w = t >> 5, lane = t & 31;
    float v = 0.f;
    if (w == 0)      { for (int c = lane; c < 128; c += 32) v += We1[c]       * ae1[c]; }
    else if (w == 1) { for (int c = lane; c < 128; c += 32) v += We1[128 + c] * ae1[128 + c]; }
    else if (w == 2) { for (int c = lane; c <  64; c += 32) v += We2[c]       * ae2[c]; }
    else if (w == 3) { for (int c = lane; c <  64; c += 32) v += We2[64 + c]  * ae2[64 + c]; }
    #pragma unroll
    for (int off = 16; off; off >>= 1) v += __shfl_xor_sync(0xffffffffu, v, off);
    if (w < 4 && lane == 0) g_ke[w] = v;
    if (w == 4 && lane < N_GRAPHS)
        g_mean[lane] = g_gsum[lane] / (float)g_gcnt[lane];
}

// ---------------- 3-stage coalesced exclusive scan ---------------------------
// stage 1: per-block scan of degrees (g_cursor) -> partial rowptr + block sums
__global__ void k_scan1() {
    int t = threadIdx.x;
    int i = blockIdx.x * 256 + t;
    int v = (i < N_NODES) ? g_cursor[i] : 0;
    int lane = t & 31, w = t >> 5;
    int x = v;
    #pragma unroll
    for (int o = 1; o < 32; o <<= 1) {
        int y = __shfl_up_sync(0xffffffffu, x, o);
        if (lane >= o) x += y;
    }
    __shared__ int ws[8];
    if (lane == 31) ws[w] = x;
    __syncthreads();
    if (t == 0) {
        int run = 0;
        #pragma unroll
        for (int j = 0; j < 8; j++) { int tmp = ws[j]; ws[j] = run; run += tmp; }
        g_bsum[blockIdx.x] = run;
    }
    __syncthreads();
    int excl = x - v + ws[w];
    if (i < N_NODES) g_rowptr[i] = excl;
}

// stage 2: exclusive scan of the 196 block sums (1 block)
__global__ void k_scan2() {
    int t = threadIdx.x;
    int v = (t < NBLK_SCAN) ? g_bsum[t] : 0;
    int lane = t & 31, w = t >> 5;
    int x = v;
    #pragma unroll
    for (int o = 1; o < 32; o <<= 1) {
        int y = __shfl_up_sync(0xffffffffu, x, o);
        if (lane >= o) x += y;
    }
    __shared__ int ws[8];
    if (lane == 31) ws[w] = x;
    __syncthreads();
    if (t == 0) {
        int run = 0;
        #pragma unroll
        for (int j = 0; j < 8; j++) { int tmp = ws[j]; ws[j] = run; run += tmp; }
        g_rowptr[N_NODES] = run;   // grand total (= TOT_EDGES)
    }
    __syncthreads();
    int excl = x - v + ws[w];
    if (t < NBLK_SCAN) g_bsum[t] = excl;
}

// stage 3: add block offsets; init cursor
__global__ void k_scan3() {
    int i = blockIdx.x * 256 + threadIdx.x;
    if (i < N_NODES) {
        int r = g_rowptr[i] + g_bsum[blockIdx.x];
        g_rowptr[i] = r;
        g_cursor[i] = r;
    }
}

// ---------------- CSR fill (real edges + self loops) ------------------------
__global__ void k_fill(const int* __restrict__ src, const int* __restrict__ dst,
                       const float* __restrict__ ea) {
    for (int i = blockIdx.x * blockDim.x + threadIdx.x; i < TOT_EDGES;
         i += gridDim.x * blockDim.x) {
        if (i < N_EDGES) {
            int d = dst[i];
            int p = atomicAdd(&g_cursor[d], 1);
            g_col[p] = src[i];
            g_eav[p] = ea[i];
        } else {
            int n = i - N_EDGES;
            int p = atomicAdd(&g_cursor[n], 1);
            g_col[p] = n;
            g_eav[p] = g_mean[n / NPG];
        }
    }
}

// ---------------- SGEMM: C[M,N] = A[M,K] @ B[K,N], double-buffered ----------
// 128x128 tile, BK=8, 8x8 per thread, 256 threads, 2 CTAs/SM.
__global__ void __launch_bounds__(256, 2) k_sgemm(const float* __restrict__ A,
                                                  const float* __restrict__ B,
                                                  float* __restrict__ C,
                                                  int M, int Nn, int K) {
    __shared__ float As[2][8][132];   // transposed, padded
    __shared__ float Bs[2][8][128];
    int tid  = threadIdx.x;
    int brow = blockIdx.y * 128, bcol = blockIdx.x * 128;
    int ar = tid >> 1, ac = (tid & 1) * 4;          // A: row, k-offset
    int br = tid >> 5, bc4 = (tid & 31) * 4;        // B: k-row, col offset
    int ty = (tid >> 4) * 8, tn = (tid & 15) * 8;   // thread tile origin
    int arow = brow + ar;
    bool aval = arow < M;
    const float* Aptr = A + (size_t)arow * K + ac;
    const float* Bptr = B + (size_t)br * Nn + bcol + bc4;

    float acc[8][8];
    #pragma unroll
    for (int i = 0; i < 8; i++)
        #pragma unroll
        for (int j = 0; j < 8; j++) acc[i][j] = 0.f;

    float4 av = aval ? *reinterpret_cast<const float4*>(Aptr)
                     : make_float4(0.f, 0.f, 0.f, 0.f);
    float4 bv = *reinterpret_cast<const float4*>(Bptr);
    int buf = 0;
    As[0][ac + 0][ar] = av.x; As[0][ac + 1][ar] = av.y;
    As[0][ac + 2][ar] = av.z; As[0][ac + 3][ar] = av.w;
    *reinterpret_cast<float4*>(&Bs[0][br][bc4]) = bv;
    __syncthreads();

    int KT = K >> 3;
    for (int kt = 0; kt < KT; kt++) {
        if (kt + 1 < KT) {
            av = aval ? *reinterpret_cast<const float4*>(Aptr + (kt + 1) * 8)
                      : make_float4(0.f, 0.f, 0.f, 0.f);
            bv = *reinterpret_cast<const float4*>(Bptr + (size_t)(kt + 1) * 8 * Nn);
        }
        #pragma unroll
        for (int k = 0; k < 8; k++) {
            float a[8], b[8];
            *(float4*)&a[0] = *(float4*)&As[buf][k][ty];
            *(float4*)&a[4] = *(float4*)&As[buf][k][ty + 4];
            *(float4*)&b[0] = *(float4*)&Bs[buf][k][tn];
            *(float4*)&b[4] = *(float4*)&Bs[buf][k][tn + 4];
            #pragma unroll
            for (int i = 0; i < 8; i++)
                #pragma unroll
                for (int j = 0; j < 8; j++) acc[i][j] = fmaf(a[i], b[j], acc[i][j]);
        }
        if (kt + 1 < KT) {
            buf ^= 1;
            As[buf][ac + 0][ar] = av.x; As[buf][ac + 1][ar] = av.y;
            As[buf][ac + 2][ar] = av.z; As[buf][ac + 3][ar] = av.w;
            *reinterpret_cast<float4*>(&Bs[buf][br][bc4]) = bv;
            __syncthreads();
        }
    }
    #pragma unroll
    for (int i = 0; i < 8; i++) {
        int row = brow + ty + i;
        if (row < M) {
            *(float4*)&C[(size_t)row * Nn + bcol + tn]     =
                make_float4(acc[i][0], acc[i][1], acc[i][2], acc[i][3]);
            *(float4*)&C[(size_t)row * Nn + bcol + tn + 4] =
                make_float4(acc[i][4], acc[i][5], acc[i][6], acc[i][7]);
        }
    }
}

// ---------------- per-node attention logits: al_s, al_d --------------------
template <int C>
__global__ void k_alpha(const float* __restrict__ xp, const float* __restrict__ asrc,
                        const float* __restrict__ adst) {
    int warp = (blockIdx.x * blockDim.x + threadIdx.x) >> 5;
    int lane = threadIdx.x & 31;
    if (warp >= N_NODES) return;
    const float* row = xp + (size_t)warp * 2 * C;
    float s0 = 0.f, d0 = 0.f, s1 = 0.f, d1 = 0.f;
    #pragma unroll
    for (int j = 0; j < C / 32; j++) {
        int c = lane + 32 * j;
        float v0 = row[c], v1 = row[C + c];
        s0 += v0 * asrc[c];      d0 += v0 * adst[c];
        s1 += v1 * asrc[C + c];  d1 += v1 * adst[C + c];
    }
    #pragma unroll
    for (int off = 16; off; off >>= 1) {
        s0 += __shfl_xor_sync(0xffffffffu, s0, off);
        d0 += __shfl_xor_sync(0xffffffffu, d0, off);
        s1 += __shfl_xor_sync(0xffffffffu, s1, off);
        d1 += __shfl_xor_sync(0xffffffffu, d1, off);
    }
    if (lane == 0) {
        g_als[2 * warp]     = s0;  g_als[2 * warp + 1] = s1;
        g_ald[2 * warp]     = d0;  g_ald[2 * warp + 1] = d1;
    }
}

// ---------------- warp-per-dst online-softmax aggregation (vectorized) ------
template <int C, bool RELU>
__global__ void k_agg(const float* __restrict__ xp, const float* __restrict__ bias,
                      float* __restrict__ out, int keoff) {
    int warp = (blockIdx.x * blockDim.x + threadIdx.x) >> 5;
    int lane = threadIdx.x & 31;
    if (warp >= N_NODES) return;
    constexpr int V = C / 32;   // 4 (C=128) or 2 (C=64)
    float acc0[V], acc1[V];
    #pragma unroll
    for (int j = 0; j < V; j++) { acc0[j] = 0.f; acc1[j] = 0.f; }
    float m0 = -1e30f, m1 = -1e30f, d0 = 0.f, d1 = 0.f;
    float ad0 = g_ald[2 * warp], ad1 = g_ald[2 * warp + 1];
    float ke0 = g_ke[keoff], ke1 = g_ke[keoff + 1];
    int p0 = g_rowptr[warp], p1 = g_rowptr[warp + 1];
    int c0 = lane * V;
    for (int p = p0; p < p1; p++) {
        int s = g_col[p];
        float ea = g_eav[p];
        float a0 = g_als[2 * s]     + ad0 + ea * ke0;
        float a1 = g_als[2 * s + 1] + ad1 + ea * ke1;
        a0 = a0 > 0.f ? a0 : 0.2f * a0;
        a1 = a1 > 0.f ? a1 : 0.2f * a1;
        float nm0 = fmaxf(m0, a0), nm1 = fmaxf(m1, a1);
        float sc0 = __expf(m0 - nm0), sc1 = __expf(m1 - nm1);
        float w0  = __expf(a0 - nm0), w1  = __expf(a1 - nm1);
        d0 = d0 * sc0 + w0;  d1 = d1 * sc1 + w1;
        m0 = nm0;  m1 = nm1;
        const float* row = xp + (size_t)s * 2 * C + c0;
        float v0[V], v1[V];
        if constexpr (V == 4) {
            float4 t0 = *reinterpret_cast<const float4*>(row);
            float4 t1 = *reinterpret_cast<const float4*>(row + C);
            v0[0] = t0.x; v0[1] = t0.y; v0[2] = t0.z; v0[3] = t0.w;
            v1[0] = t1.x; v1[1] = t1.y; v1[2] = t1.z; v1[3] = t1.w;
        } else {
            float2 t0 = *reinterpret_cast<const float2*>(row);
            float2 t1 = *reinterpret_cast<const float2*>(row + C);
            v0[0] = t0.x; v0[1] = t0.y;
            v1[0] = t1.x; v1[1] = t1.y;
        }
        #pragma unroll
        for (int j = 0; j < V; j++) {
            acc0[j] = acc0[j] * sc0 + w0 * v0[j];
            acc1[j] = acc1[j] * sc1 + w1 * v1[j];
        }
    }
    float r0 = 1.f / (d0 + 1e-16f), r1 = 1.f / (d1 + 1e-16f);
    float res[V];
    #pragma unroll
    for (int j = 0; j < V; j++) {
        float vv = 0.5f * (acc0[j] * r0 + acc1[j] * r1) + bias[c0 + j];
        if (RELU) vv = fmaxf(vv, 0.f);
        res[j] = vv;
    }
    if constexpr (V == 4)
        *reinterpret_cast<float4*>(&out[(size_t)warp * C + c0]) =
            make_float4(res[0], res[1], res[2], res[3]);
    else
        *reinterpret_cast<float2*>(&out[(size_t)warp * C + c0]) =
            make_float2(res[0], res[1]);
}

// ---------------- classifier: pred = h2 @ Wc + bc --------------------------
__global__ void __launch_bounds__(256) k_cls(const float* __restrict__ Wc,
                                             const float* __restrict__ bc,
                                             float* __restrict__ out) {
    __shared__ float sh[64][65];
    __shared__ float swc[64 * NC];
    __shared__ float sbc[NC];
    int tid = threadIdx.x;
    int n0 = blockIdx.x * 64;
    for (int i = tid; i < 64 * NC; i += 256) swc[i] = Wc[i];
    if (tid < NC) sbc[tid] = bc[tid];
    for (int i = tid; i < 64 * 64; i += 256) {
        int r = i >> 6, k = i & 63;
        int n = n0 + r;
        sh[r][k] = (n < N_NODES) ? g_h2[(size_t)n * 64 + k] : 0.f;
    }
    __syncthreads();
    for (int idx = tid; idx < 64 * NC; idx += 256) {
        int r = idx / NC, c = idx % NC;
        int n = n0 + r;
        if (n < N_NODES) {
            float s = sbc[c];
            #pragma unroll
            for (int k = 0; k < 64; k++) s += sh[r][k] * swc[k * NC + c];
            out[(size_t)n * NC + c] = s;
        }
    }
}

__global__ void k_y(const int* __restrict__ y, float* __restrict__ out) {
    int i = blockIdx.x * blockDim.x + threadIdx.x;
    if (i < N_NODES) out[i] = (float)y[i];
}

// ---------------- launch ----------------------------------------------------
static void* sym(const void* s) { void* p = nullptr; cudaGetSymbolAddress(&p, s); return p; }

extern "C" void kernel_launch(void* const* d_in, const int* in_sizes, int n_in,
                              void* d_out, int out_size) {
    const float* x    = (const float*)d_in[0];
    const int*   ei   = (const int*)  d_in[1];
    const float* ea   = (const float*)d_in[2];
    const int*   y    = (const int*)  d_in[4];
    const float* W1   = (const float*)d_in[5];
    const float* as1  = (const float*)d_in[6];
    const float* ad1  = (const float*)d_in[7];
    const float* We1  = (const float*)d_in[8];
    const float* ae1  = (const float*)d_in[9];
    const float* b1   = (const float*)d_in[10];
    const float* W2   = (const float*)d_in[11];
    const float* as2  = (const float*)d_in[12];
    const float* ad2  = (const float*)d_in[13];
    const float* We2  = (const float*)d_in[14];
    const float* ae2  = (const float*)d_in[15];
    const float* b2   = (const float*)d_in[16];
    const float* Wc   = (const float*)d_in[17];
    const float* bc   = (const float*)d_in[18];
    float* out = (float*)d_out;
    const int* src = ei;
    const int* dst = ei + N_EDGES;

    float* xp1 = (float*)sym(g_xp1);
    float* h1  = (float*)sym(g_h1);
    float* xp2 = (float*)sym(g_xp2);

    k_init<<<(N_NODES + 255) / 256, 256>>>();
    k_edge_pass1<<<512, 256>>>(src, dst, ea);
    k_finalize<<<1, 160>>>(We1, ae1, We2, ae2);
    k_scan1<<<NBLK_SCAN, 256>>>();
    k_scan2<<<1, 256>>>();
    k_scan3<<<NBLK_SCAN, 256>>>();
    k_fill<<<1024, 256>>>(src, dst, ea);

    // Layer 1
    { dim3 g(2, (N_NODES + 127) / 128); k_sgemm<<<g, 256>>>(x, W1, xp1, N_NODES, 256, 256); }
    k_alpha<128><<<(N_NODES * 32 + 255) / 256, 256>>>(xp1, as1, ad1);
    k_agg<128, true><<<(N_NODES * 32 + 255) / 256, 256>>>(xp1, b1, h1, 0);

    // Layer 2
    { dim3 g(1, (N_NODES + 127) / 128); k_sgemm<<<g, 256>>>(h1, W2, xp2, N_NODES, 128, 128); }
    k_alpha<64><<<(N_NODES * 32 + 255) / 256, 256>>>(xp2, as2, ad2);
    k_agg<64, false><<<(N_NODES * 32 + 255) / 256, 256>>>(xp2, b2, (float*)sym(g_h2), 2);

    // Classifier + y
    k_cls<<<(N_NODES + 63) / 64, 256>>>(Wc, bc, out);
    if (out_size >= N_NODES * NC + N_NODES)
        k_y<<<(N_NODES + 255) / 256, 256>>>(y, out + (size_t)N_NODES * NC);
}

// round 7
// speedup vs baseline: 1.8541x; 1.5186x over previous
#include <cuda_runtime.h>
#include <cuda_bf16.h>
#include <stdint.h>

#define N_NODES 50000
#define N_EDGES 500000
#define NPG     6250
#define N_GRAPHS 8
#define TOT_EDGES (N_EDGES + N_NODES)
#define NC 10
#define NBLK_SCAN ((N_NODES + 255) / 256)   // 196

// ===================== mma.sync helpers (sm_80+ ISA, compiles on compute_103) =====
__device__ __forceinline__ uint32_t smem_to_u32(const void* p) {
    uint32_t a;
    asm("{ .reg .u64 t; cvta.to.shared.u64 t, %1; cvt.u32.u64 %0, t; }" : "=r"(a) : "l"(p));
    return a;
}
#define LDSM4(r, addr) \
    asm volatile("ldmatrix.sync.aligned.m8n8.x4.shared.b16 {%0,%1,%2,%3}, [%4];" \
        : "=r"((r)[0]), "=r"((r)[1]), "=r"((r)[2]), "=r"((r)[3]) : "r"(addr))
#define MMA_BF16(d, a, b0v, b1v) \
    asm volatile("mma.sync.aligned.m16n8k16.row.col.f32.bf16.bf16.f32 " \
        "{%0,%1,%2,%3}, {%4,%5,%6,%7}, {%8,%9}, {%0,%1,%2,%3};" \
        : "+f"((d)[0]), "+f"((d)[1]), "+f"((d)[2]), "+f"((d)[3]) \
        : "r"((a)[0]), "r"((a)[1]), "r"((a)[2]), "r"((a)[3]), "r"(b0v), "r"(b1v))

// ---------------- scratch (static __device__, no allocation) ----------------
__device__ __align__(16) float g_xp1[(size_t)N_NODES * 256];
__device__ __align__(16) float g_h1 [(size_t)N_NODES * 128];
__device__ __align__(16) float g_xp2[(size_t)N_NODES * 128];
__device__ __align__(16) float g_h2 [(size_t)N_NODES * 64];
__device__ float g_als[N_NODES * 2];
__device__ float g_ald[N_NODES * 2];
__device__ int   g_rowptr[N_NODES + 1];
__device__ int   g_cursor[N_NODES];
__device__ int   g_col[TOT_EDGES];
__device__ float g_eav[TOT_EDGES];
__device__ float g_gsum[N_GRAPHS];
__device__ int   g_gcnt[N_GRAPHS];
__device__ float g_mean[N_GRAPHS];
__device__ float g_ke[4];
__device__ int   g_bsum[NBLK_SCAN];

// ---------------- init ------------------------------------------------------
__global__ void k_init() {
    int i = blockIdx.x * blockDim.x + threadIdx.x;
    if (i < N_NODES) g_cursor[i] = 1;
    if (i < N_GRAPHS) { g_gsum[i] = 0.f; g_gcnt[i] = 0; }
}

// ---------------- edge pass: per-graph attr stats + in-degree hist ----------
__global__ void k_edge_pass1(const int* __restrict__ src, const int* __restrict__ dst,
                             const float* __restrict__ ea) {
    __shared__ float ss[N_GRAPHS];
    __shared__ int   sc[N_GRAPHS];
    if (threadIdx.x < N_GRAPHS) { ss[threadIdx.x] = 0.f; sc[threadIdx.x] = 0; }
    __syncthreads();
    for (int e = blockIdx.x * blockDim.x + threadIdx.x; e < N_EDGES;
         e += gridDim.x * blockDim.x) {
        int s = src[e];
        int d = dst[e];
        int g = s / NPG;
        atomicAdd(&ss[g], ea[e]);
        atomicAdd(&sc[g], 1);
        atomicAdd(&g_cursor[d], 1);
    }
    __syncthreads();
    if (threadIdx.x < N_GRAPHS) {
        atomicAdd(&g_gsum[threadIdx.x], ss[threadIdx.x]);
        atomicAdd(&g_gcnt[threadIdx.x], sc[threadIdx.x]);
    }
}

// ---------------- per-graph means + edge-attention scalars ke ---------------
__global__ void k_finalize(const float* __restrict__ We1, const float* __restrict__ ae1,
                           const float* __restrict__ We2, const float* __restrict__ ae2) {
    int t = threadIdx.x, w = t >> 5, lane = t & 31;
    float v = 0.f;
    if (w == 0)      { for (int c = lane; c < 128; c += 32) v += We1[c]       * ae1[c]; }
    else if (w == 1) { for (int c = lane; c < 128; c += 32) v += We1[128 + c] * ae1[128 + c]; }
    else if (w == 2) { for (int c = lane; c <  64; c += 32) v += We2[c]       * ae2[c]; }
    else if (w == 3) { for (int c = lane; c <  64; c += 32) v += We2[64 + c]  * ae2[64 + c]; }
    #pragma unroll
    for (int off = 16; off; off >>= 1) v += __shfl_xor_sync(0xffffffffu, v, off);
    if (w < 4 && lane == 0) g_ke[w] = v;
    if (w == 4 && lane < N_GRAPHS)
        g_mean[lane] = g_gsum[lane] / (float)g_gcnt[lane];
}

// ---------------- 3-stage coalesced exclusive scan ---------------------------
__global__ void k_scan1() {
    int t = threadIdx.x;
    int i = blockIdx.x * 256 + t;
    int v = (i < N_NODES) ? g_cursor[i] : 0;
    int lane = t & 31, w = t >> 5;
    int x = v;
    #pragma unroll
    for (int o = 1; o < 32; o <<= 1) {
        int y = __shfl_up_sync(0xffffffffu, x, o);
        if (lane >= o) x += y;
    }
    __shared__ int ws[8];
    if (lane == 31) ws[w] = x;
    __syncthreads();
    if (t == 0) {
        int run = 0;
        #pragma unroll
        for (int j = 0; j < 8; j++) { int tmp = ws[j]; ws[j] = run; run += tmp; }
        g_bsum[blockIdx.x] = run;
    }
    __syncthreads();
    int excl = x - v + ws[w];
    if (i < N_NODES) g_rowptr[i] = excl;
}
__global__ void k_scan2() {
    int t = threadIdx.x;
    int v = (t < NBLK_SCAN) ? g_bsum[t] : 0;
    int lane = t & 31, w = t >> 5;
    int x = v;
    #pragma unroll
    for (int o = 1; o < 32; o <<= 1) {
        int y = __shfl_up_sync(0xffffffffu, x, o);
        if (lane >= o) x += y;
    }
    __shared__ int ws[8];
    if (lane == 31) ws[w] = x;
    __syncthreads();
    if (t == 0) {
        int run = 0;
        #pragma unroll
        for (int j = 0; j < 8; j++) { int tmp = ws[j]; ws[j] = run; run += tmp; }
        g_rowptr[N_NODES] = run;
    }
    __syncthreads();
    int excl = x - v + ws[w];
    if (t < NBLK_SCAN) g_bsum[t] = excl;
}
__global__ void k_scan3() {
    int i = blockIdx.x * 256 + threadIdx.x;
    if (i < N_NODES) {
        int r = g_rowptr[i] + g_bsum[blockIdx.x];
        g_rowptr[i] = r;
        g_cursor[i] = r;
    }
}

// ---------------- CSR fill ---------------------------------------------------
__global__ void k_fill(const int* __restrict__ src, const int* __restrict__ dst,
                       const float* __restrict__ ea) {
    for (int i = blockIdx.x * blockDim.x + threadIdx.x; i < TOT_EDGES;
         i += gridDim.x * blockDim.x) {
        if (i < N_EDGES) {
            int d = dst[i];
            int p = atomicAdd(&g_cursor[d], 1);
            g_col[p] = src[i];
            g_eav[p] = ea[i];
        } else {
            int n = i - N_EDGES;
            int p = atomicAdd(&g_cursor[n], 1);
            g_col[p] = n;
            g_eav[p] = g_mean[n / NPG];
        }
    }
}

// ============ split-bf16 mma.sync GEMM + fused attention-logit epilogue ======
// C[m, ncol] = sum_k A[m,k] * W[k, bcol+ncol], stored to xp[m, head, c];
// also writes g_als[2m+head], g_ald[2m+head].
// CTA tile 128M x 128N, 256 threads = 8 warps (4M x 2N), warp tile 32x64.
// K staged in 32-chunks, double-buffered SMEM (A,W as bf16 hi/lo, stride 40 bf16).
static constexpr int MMA_STR  = 80;           // smem row stride bytes (40 bf16)
static constexpr int MMA_MATB = 128 * MMA_STR;
static constexpr int MMA_BUFB = 4 * MMA_MATB; // Ah, Al, Bh, Bl
static constexpr int MMA_SMEM = 2 * MMA_BUFB + 512 + 512 + 1024 + 1024; // 84992

template <int KDIM, int CH>
__device__ __forceinline__ void cvt_store_chunk(char* smem, int bufoff,
                                                const float4* pfa, const float* pfw,
                                                int tid) {
    #pragma unroll
    for (int i = 0; i < 4; i++) {
        int idx = tid + i * 256;
        int row = idx >> 3, kq = idx & 7;
        float4 v = pfa[i];
        __nv_bfloat162 h0, h1, l0, l1;
        h0.x = __float2bfloat16(v.x); h0.y = __float2bfloat16(v.y);
        h1.x = __float2bfloat16(v.z); h1.y = __float2bfloat16(v.w);
        l0.x = __float2bfloat16(v.x - __bfloat162float(h0.x));
        l0.y = __float2bfloat16(v.y - __bfloat162float(h0.y));
        l1.x = __float2bfloat16(v.z - __bfloat162float(h1.x));
        l1.y = __float2bfloat16(v.w - __bfloat162float(h1.y));
        char* p = smem + bufoff + row * MMA_STR + kq * 8;
        *reinterpret_cast<__nv_bfloat162*>(p)     = h0;
        *reinterpret_cast<__nv_bfloat162*>(p + 4) = h1;
        *reinterpret_cast<__nv_bfloat162*>(p + MMA_MATB)     = l0;
        *reinterpret_cast<__nv_bfloat162*>(p + MMA_MATB + 4) = l1;
    }
    #pragma unroll
    for (int i = 0; i < 8; i++) {
        int idx = tid + i * 256;
        int k2 = idx >> 7, n = idx & 127;
        float w0 = pfw[2 * i], w1 = pfw[2 * i + 1];
        __nv_bfloat162 h, l;
        h.x = __float2bfloat16(w0); h.y = __float2bfloat16(w1);
        l.x = __float2bfloat16(w0 - __bfloat162float(h.x));
        l.y = __float2bfloat16(w1 - __bfloat162float(h.y));
        char* p = smem + bufoff + 2 * MMA_MATB + n * MMA_STR + k2 * 4;
        *reinterpret_cast<__nv_bfloat162*>(p)            = h;
        *reinterpret_cast<__nv_bfloat162*>(p + MMA_MATB) = l;
    }
}

template <int KDIM, int CH>
__global__ void __launch_bounds__(256) k_mma(const float* __restrict__ A,
                                             const float* __restrict__ W,
                                             float* __restrict__ xp,
                                             const float* __restrict__ asrc,
                                             const float* __restrict__ adst,
                                             int M) {
    extern __shared__ char smem[];
    constexpr int NW  = 2 * CH;     // W row stride (floats)
    constexpr int KCH = KDIM / 32;  // K chunks
    constexpr int SAS  = 2 * MMA_BUFB;
    constexpr int SAD  = SAS + 512;
    constexpr int SALS = SAD + 512;
    constexpr int SALD = SALS + 1024;

    const int tid = threadIdx.x;
    const int wid = tid >> 5, lane = tid & 31;
    const int wm = wid & 3, wn = wid >> 2;
    const int brow = blockIdx.y * 128;
    const int bcol = blockIdx.x * 128;
    const uint32_t sb = smem_to_u32(smem);

    float* s_as  = reinterpret_cast<float*>(smem + SAS);
    float* s_ad  = reinterpret_cast<float*>(smem + SAD);
    float* s_als = reinterpret_cast<float*>(smem + SALS);
    float* s_ald = reinterpret_cast<float*>(smem + SALD);
    if (tid < 128) { s_as[tid] = asrc[bcol + tid]; s_ad[tid] = adst[bcol + tid]; }
    s_als[tid] = 0.f;
    s_ald[tid] = 0.f;

    // ldmatrix per-lane offsets (A: m16k16 tiles, B: two n8k16 tiles per x4)
    const uint32_t aoff = (uint32_t)((lane & 15) * MMA_STR + (lane >> 4) * 16);
    const uint32_t boff = (uint32_t)(((lane & 7) + ((lane >> 4) & 1) * 8) * MMA_STR
                                     + ((lane >> 3) & 1) * 16);

    float4 pfa[4];
    float  pfw[16];
    // prologue: load chunk 0
    #pragma unroll
    for (int i = 0; i < 4; i++) {
        int idx = tid + i * 256;
        int row = idx >> 3, kq = idx & 7;
        int gr = brow + row;
        pfa[i] = (gr < M) ? *reinterpret_cast<const float4*>(A + (size_t)gr * KDIM + kq * 4)
                          : make_float4(0.f, 0.f, 0.f, 0.f);
    }
    #pragma unroll
    for (int i = 0; i < 8; i++) {
        int idx = tid + i * 256;
        int k = (idx >> 7) * 2, n = idx & 127;
        pfw[2 * i]     = W[(size_t)k * NW + bcol + n];
        pfw[2 * i + 1] = W[(size_t)(k + 1) * NW + bcol + n];
    }
    cvt_store_chunk<KDIM, CH>(smem, 0, pfa, pfw, tid);
    __syncthreads();

    float acc[2][8][4];
    #pragma unroll
    for (int a = 0; a < 2; a++)
        #pragma unroll
        for (int b = 0; b < 8; b++)
            #pragma unroll
            for (int c = 0; c < 4; c++) acc[a][b][c] = 0.f;

    int buf = 0;
    for (int kc = 0; kc < KCH; kc++) {
        if (kc + 1 < KCH) {
            const int kb = (kc + 1) * 32;
            #pragma unroll
            for (int i = 0; i < 4; i++) {
                int idx = tid + i * 256;
                int row = idx >> 3, kq = idx & 7;
                int gr = brow + row;
                pfa[i] = (gr < M)
                    ? *reinterpret_cast<const float4*>(A + (size_t)gr * KDIM + kb + kq * 4)
                    : make_float4(0.f, 0.f, 0.f, 0.f);
            }
            #pragma unroll
            for (int i = 0; i < 8; i++) {
                int idx = tid + i * 256;
                int k = kb + (idx >> 7) * 2, n = idx & 127;
                pfw[2 * i]     = W[(size_t)k * NW + bcol + n];
                pfw[2 * i + 1] = W[(size_t)(k + 1) * NW + bcol + n];
            }
        }
        const uint32_t baseA = sb + buf * MMA_BUFB;
        const uint32_t baseB = baseA + 2 * MMA_MATB;
        #pragma unroll
        for (int ks = 0; ks < 2; ks++) {
            uint32_t ah[2][4], al[2][4], bh[4][4], bl[4][4];
            #pragma unroll
            for (int mf = 0; mf < 2; mf++) {
                uint32_t ad = baseA + (uint32_t)((wm * 32 + mf * 16) * MMA_STR) + ks * 32 + aoff;
                LDSM4(ah[mf], ad);
                LDSM4(al[mf], ad + MMA_MATB);
            }
            #pragma unroll
            for (int np = 0; np < 4; np++) {
                uint32_t bd = baseB + (uint32_t)((wn * 64 + np * 16) * MMA_STR) + ks * 32 + boff;
                LDSM4(bh[np], bd);
                LDSM4(bl[np], bd + MMA_MATB);
            }
            #pragma unroll
            for (int mf = 0; mf < 2; mf++)
                #pragma unroll
                for (int np = 0; np < 4; np++)
                    #pragma unroll
                    for (int hh = 0; hh < 2; hh++) {
                        int nf = np * 2 + hh;
                        MMA_BF16(acc[mf][nf], ah[mf], bh[np][2 * hh], bh[np][2 * hh + 1]);
                        MMA_BF16(acc[mf][nf], al[mf], bh[np][2 * hh], bh[np][2 * hh + 1]);
                        MMA_BF16(acc[mf][nf], ah[mf], bl[np][2 * hh], bl[np][2 * hh + 1]);
                    }
        }
        if (kc + 1 < KCH) {
            cvt_store_chunk<KDIM, CH>(smem, (buf ^ 1) * MMA_BUFB, pfa, pfw, tid);
            __syncthreads();
            buf ^= 1;
        }
    }

    // ---- epilogue: write xp + fused attention logits ----
    #pragma unroll
    for (int mf = 0; mf < 2; mf++)
        #pragma unroll
        for (int r = 0; r < 2; r++) {
            int row_local = wm * 32 + mf * 16 + (lane >> 2) + r * 8;
            int m = brow + row_local;
            float als = 0.f, ald = 0.f;
            #pragma unroll
            for (int nf = 0; nf < 8; nf++) {
                float c0 = acc[mf][nf][r * 2 + 0], c1 = acc[mf][nf][r * 2 + 1];
                int j = wn * 64 + nf * 8 + (lane & 3) * 2;
                als += c0 * s_as[j] + c1 * s_as[j + 1];
                ald += c0 * s_ad[j] + c1 * s_ad[j + 1];
                if (m < M) {
                    int ncol = bcol + j;
                    int head = ncol / CH, c = ncol % CH;
                    *reinterpret_cast<float2*>(xp + ((size_t)m * 2 + head) * CH + c) =
                        make_float2(c0, c1);
                }
            }
            als += __shfl_xor_sync(0xffffffffu, als, 1);
            als += __shfl_xor_sync(0xffffffffu, als, 2);
            ald += __shfl_xor_sync(0xffffffffu, ald, 1);
            ald += __shfl_xor_sync(0xffffffffu, ald, 2);
            if ((lane & 3) == 0) {
                int sidx = (CH == 64 ? wn * 128 : 0) + row_local;
                atomicAdd(&s_als[sidx], als);
                atomicAdd(&s_ald[sidx], ald);
            }
        }
    __syncthreads();
    if (CH == 128) {
        if (tid < 128) {
            int m = brow + tid;
            if (m < M) {
                g_als[2 * m + blockIdx.x] = s_als[tid];
                g_ald[2 * m + blockIdx.x] = s_ald[tid];
            }
        }
    } else {
        int h = tid >> 7, t = tid & 127;
        int m = brow + t;
        if (m < M) {
            g_als[2 * m + h] = s_als[tid];
            g_ald[2 * m + h] = s_ald[tid];
        }
    }
}

// ---------------- warp-per-dst online-softmax aggregation -------------------
template <int C, bool RELU>
__global__ void k_agg(const float* __restrict__ xp, const float* __restrict__ bias,
                      float* __restrict__ out, int keoff) {
    int warp = (blockIdx.x * blockDim.x + threadIdx.x) >> 5;
    int lane = threadIdx.x & 31;
    if (warp >= N_NODES) return;
    constexpr int V = C / 32;
    float acc0[V], acc1[V];
    #pragma unroll
    for (int j = 0; j < V; j++) { acc0[j] = 0.f; acc1[j] = 0.f; }
    float m0 = -1e30f, m1 = -1e30f, d0 = 0.f, d1 = 0.f;
    float ad0 = g_ald[2 * warp], ad1 = g_ald[2 * warp + 1];
    float ke0 = g_ke[keoff], ke1 = g_ke[keoff + 1];
    int p0 = g_rowptr[warp], p1 = g_rowptr[warp + 1];
    int c0 = lane * V;
    for (int p = p0; p < p1; p++) {
        int s = g_col[p];
        float ea = g_eav[p];
        float a0 = g_als[2 * s]     + ad0 + ea * ke0;
        float a1 = g_als[2 * s + 1] + ad1 + ea * ke1;
        a0 = a0 > 0.f ? a0 : 0.2f * a0;
        a1 = a1 > 0.f ? a1 : 0.2f * a1;
        float nm0 = fmaxf(m0, a0), nm1 = fmaxf(m1, a1);
        float sc0 = __expf(m0 - nm0), sc1 = __expf(m1 - nm1);
        float w0  = __expf(a0 - nm0), w1  = __expf(a1 - nm1);
        d0 = d0 * sc0 + w0;  d1 = d1 * sc1 + w1;
        m0 = nm0;  m1 = nm1;
        const float* row = xp + (size_t)s * 2 * C + c0;
        float v0[V], v1[V];
        if constexpr (V == 4) {
            float4 t0 = *reinterpret_cast<const float4*>(row);
            float4 t1 = *reinterpret_cast<const float4*>(row + C);
            v0[0] = t0.x; v0[1] = t0.y; v0[2] = t0.z; v0[3] = t0.w;
            v1[0] = t1.x; v1[1] = t1.y; v1[2] = t1.z; v1[3] = t1.w;
        } else {
            float2 t0 = *reinterpret_cast<const float2*>(row);
            float2 t1 = *reinterpret_cast<const float2*>(row + C);
            v0[0] = t0.x; v0[1] = t0.y;
            v1[0] = t1.x; v1[1] = t1.y;
        }
        #pragma unroll
        for (int j = 0; j < V; j++) {
            acc0[j] = acc0[j] * sc0 + w0 * v0[j];
            acc1[j] = acc1[j] * sc1 + w1 * v1[j];
        }
    }
    float r0 = 1.f / (d0 + 1e-16f), r1 = 1.f / (d1 + 1e-16f);
    float res[V];
    #pragma unroll
    for (int j = 0; j < V; j++) {
        float vv = 0.5f * (acc0[j] * r0 + acc1[j] * r1) + bias[c0 + j];
        if (RELU) vv = fmaxf(vv, 0.f);
        res[j] = vv;
    }
    if constexpr (V == 4)
        *reinterpret_cast<float4*>(&out[(size_t)warp * C + c0]) =
            make_float4(res[0], res[1], res[2], res[3]);
    else
        *reinterpret_cast<float2*>(&out[(size_t)warp * C + c0]) =
            make_float2(res[0], res[1]);
}

// ---------------- classifier ------------------------------------------------
__global__ void __launch_bounds__(256) k_cls(const float* __restrict__ Wc,
                                             const float* __restrict__ bc,
                                             float* __restrict__ out) {
    __shared__ float sh[64][65];
    __shared__ float swc[64 * NC];
    __shared__ float sbc[NC];
    int tid = threadIdx.x;
    int n0 = blockIdx.x * 64;
    for (int i = tid; i < 64 * NC; i += 256) swc[i] = Wc[i];
    if (tid < NC) sbc[tid] = bc[tid];
    for (int i = tid; i < 64 * 64; i += 256) {
        int r = i >> 6, k = i & 63;
        int n = n0 + r;
        sh[r][k] = (n < N_NODES) ? g_h2[(size_t)n * 64 + k] : 0.f;
    }
    __syncthreads();
    for (int idx = tid; idx < 64 * NC; idx += 256) {
        int r = idx / NC, c = idx % NC;
        int n = n0 + r;
        if (n < N_NODES) {
            float s = sbc[c];
            #pragma unroll
            for (int k = 0; k < 64; k++) s += sh[r][k] * swc[k * NC + c];
            out[(size_t)n * NC + c] = s;
        }
    }
}

__global__ void k_y(const int* __restrict__ y, float* __restrict__ out) {
    int i = blockIdx.x * blockDim.x + threadIdx.x;
    if (i < N_NODES) out[i] = (float)y[i];
}

// ---------------- launch ------------------------------------------------------
static void* sym(const void* s) { void* p = nullptr; cudaGetSymbolAddress(&p, s); return p; }

extern "C" void kernel_launch(void* const* d_in, const int* in_sizes, int n_in,
                              void* d_out, int out_size) {
    const float* x    = (const float*)d_in[0];
    const int*   ei   = (const int*)  d_in[1];
    const float* ea   = (const float*)d_in[2];
    const int*   y    = (const int*)  d_in[4];
    const float* W1   = (const float*)d_in[5];
    const float* as1  = (const float*)d_in[6];
    const float* ad1  = (const float*)d_in[7];
    const float* We1  = (const float*)d_in[8];
    const float* ae1  = (const float*)d_in[9];
    const float* b1   = (const float*)d_in[10];
    const float* W2   = (const float*)d_in[11];
    const float* as2  = (const float*)d_in[12];
    const float* ad2  = (const float*)d_in[13];
    const float* We2  = (const float*)d_in[14];
    const float* ae2  = (const float*)d_in[15];
    const float* b2   = (const float*)d_in[16];
    const float* Wc   = (const float*)d_in[17];
    const float* bc   = (const float*)d_in[18];
    float* out = (float*)d_out;
    const int* src = ei;
    const int* dst = ei + N_EDGES;

    float* xp1 = (float*)sym(g_xp1);
    float* h1  = (float*)sym(g_h1);
    float* xp2 = (float*)sym(g_xp2);

    cudaFuncSetAttribute(k_mma<256, 128>,
                         cudaFuncAttributeMaxDynamicSharedMemorySize, MMA_SMEM);
    cudaFuncSetAttribute(k_mma<128, 64>,
                         cudaFuncAttributeMaxDynamicSharedMemorySize, MMA_SMEM);

    k_init<<<(N_NODES + 255) / 256, 256>>>();
    k_edge_pass1<<<512, 256>>>(src, dst, ea);
    k_finalize<<<1, 160>>>(We1, ae1, We2, ae2);
    k_scan1<<<NBLK_SCAN, 256>>>();
    k_scan2<<<1, 256>>>();
    k_scan3<<<NBLK_SCAN, 256>>>();
    k_fill<<<1024, 256>>>(src, dst, ea);

    const int MB = (N_NODES + 127) / 128;   // 391

    // Layer 1: fused tensor-core GEMM (+ attention logits) then aggregation
    k_mma<256, 128><<<dim3(2, MB), 256, MMA_SMEM>>>(x, W1, xp1, as1, ad1, N_NODES);
    k_agg<128, true><<<(N_NODES * 32 + 255) / 256, 256>>>(xp1, b1, h1, 0);

    // Layer 2
    k_mma<128, 64><<<dim3(1, MB), 256, MMA_SMEM>>>(h1, W2, xp2, as2, ad2, N_NODES);
    k_agg<64, false><<<(N_NODES * 32 + 255) / 256, 256>>>(xp2, b2, (float*)sym(g_h2), 2);

    // Classifier + y
    k_cls<<<(N_NODES + 63) / 64, 256>>>(Wc, bc, out);
    if (out_size >= N_NODES * NC + N_NODES)
        k_y<<<(N_NODES + 255) / 256, 256>>>(y, out + (size_t)N_NODES * NC);
}

// round 8
// speedup vs baseline: 1.9942x; 1.0756x over previous
#include <cuda_runtime.h>
#include <cuda_bf16.h>
#include <stdint.h>

#define N_NODES 50000
#define N_EDGES 500000
#define NPG     6250
#define N_GRAPHS 8
#define TOT_EDGES (N_EDGES + N_NODES)
#define NC 10
#define NBLK_SCAN ((N_NODES + 255) / 256)   // 196

// ===================== mma.sync helpers (sm_80+ ISA) ========================
__device__ __forceinline__ uint32_t smem_to_u32(const void* p) {
    uint32_t a;
    asm("{ .reg .u64 t; cvta.to.shared.u64 t, %1; cvt.u32.u64 %0, t; }" : "=r"(a) : "l"(p));
    return a;
}
#define LDSM4(r, addr) \
    asm volatile("ldmatrix.sync.aligned.m8n8.x4.shared.b16 {%0,%1,%2,%3}, [%4];" \
        : "=r"((r)[0]), "=r"((r)[1]), "=r"((r)[2]), "=r"((r)[3]) : "r"(addr))
#define MMA_BF16(d, a, b0v, b1v) \
    asm volatile("mma.sync.aligned.m16n8k16.row.col.f32.bf16.bf16.f32 " \
        "{%0,%1,%2,%3}, {%4,%5,%6,%7}, {%8,%9}, {%0,%1,%2,%3};" \
        : "+f"((d)[0]), "+f"((d)[1]), "+f"((d)[2]), "+f"((d)[3]) \
        : "r"((a)[0]), "r"((a)[1]), "r"((a)[2]), "r"((a)[3]), "r"(b0v), "r"(b1v))

// ---------------- scratch (static __device__, no allocation) ----------------
__device__ __align__(16) float g_xp1[(size_t)N_NODES * 256];
__device__ __align__(16) float g_h1 [(size_t)N_NODES * 128];
__device__ __align__(16) float g_xp2[(size_t)N_NODES * 128];
__device__ float g_als[N_NODES * 2];
__device__ float g_ald[N_NODES * 2];
__device__ int   g_rowptr[N_NODES + 1];
__device__ int   g_cursor[N_NODES];
__device__ int   g_col[TOT_EDGES];
__device__ float g_eav[TOT_EDGES];
__device__ float g_gsum[N_GRAPHS];
__device__ int   g_gcnt[N_GRAPHS];
__device__ float g_mean[N_GRAPHS];
__device__ float g_ke[4];
__device__ int   g_bsum[NBLK_SCAN];

// ---------------- init ------------------------------------------------------
__global__ void k_init() {
    int i = blockIdx.x * blockDim.x + threadIdx.x;
    if (i < N_NODES) g_cursor[i] = 1;
    if (i < N_GRAPHS) { g_gsum[i] = 0.f; g_gcnt[i] = 0; }
}

// ---------------- edge pass: per-graph attr stats + in-degree hist ----------
__global__ void k_edge_pass1(const int* __restrict__ src, const int* __restrict__ dst,
                             const float* __restrict__ ea) {
    __shared__ float ss[N_GRAPHS];
    __shared__ int   sc[N_GRAPHS];
    if (threadIdx.x < N_GRAPHS) { ss[threadIdx.x] = 0.f; sc[threadIdx.x] = 0; }
    __syncthreads();
    for (int e = blockIdx.x * blockDim.x + threadIdx.x; e < N_EDGES;
         e += gridDim.x * blockDim.x) {
        int s = src[e];
        int d = dst[e];
        int g = s / NPG;
        atomicAdd(&ss[g], ea[e]);
        atomicAdd(&sc[g], 1);
        atomicAdd(&g_cursor[d], 1);
    }
    __syncthreads();
    if (threadIdx.x < N_GRAPHS) {
        atomicAdd(&g_gsum[threadIdx.x], ss[threadIdx.x]);
        atomicAdd(&g_gcnt[threadIdx.x], sc[threadIdx.x]);
    }
}

// ---------------- scan stage 1 -----------------------------------------------
__global__ void k_scan1() {
    int t = threadIdx.x;
    int i = blockIdx.x * 256 + t;
    int v = (i < N_NODES) ? g_cursor[i] : 0;
    int lane = t & 31, w = t >> 5;
    int x = v;
    #pragma unroll
    for (int o = 1; o < 32; o <<= 1) {
        int y = __shfl_up_sync(0xffffffffu, x, o);
        if (lane >= o) x += y;
    }
    __shared__ int ws[8];
    if (lane == 31) ws[w] = x;
    __syncthreads();
    if (t == 0) {
        int run = 0;
        #pragma unroll
        for (int j = 0; j < 8; j++) { int tmp = ws[j]; ws[j] = run; run += tmp; }
        g_bsum[blockIdx.x] = run;
    }
    __syncthreads();
    int excl = x - v + ws[w];
    if (i < N_NODES) g_rowptr[i] = excl;
}

// ---------------- scan stage 2 + finalize (ke scalars, per-graph means) -----
__global__ void k_scan2f(const float* __restrict__ We1, const float* __restrict__ ae1,
                         const float* __restrict__ We2, const float* __restrict__ ae2) {
    int t = threadIdx.x, w = t >> 5, lane = t & 31;
    // part A: edge-attention scalars + per-graph means (warps 0-4)
    {
        float v = 0.f;
        if (w == 0)      { for (int c = lane; c < 128; c += 32) v += We1[c]       * ae1[c]; }
        else if (w == 1) { for (int c = lane; c < 128; c += 32) v += We1[128 + c] * ae1[128 + c]; }
        else if (w == 2) { for (int c = lane; c <  64; c += 32) v += We2[c]       * ae2[c]; }
        else if (w == 3) { for (int c = lane; c <  64; c += 32) v += We2[64 + c]  * ae2[64 + c]; }
        #pragma unroll
        for (int off = 16; off; off >>= 1) v += __shfl_xor_sync(0xffffffffu, v, off);
        if (w < 4 && lane == 0) g_ke[w] = v;
        if (w == 4 && lane < N_GRAPHS)
            g_mean[lane] = g_gsum[lane] / (float)g_gcnt[lane];
    }
    // part B: exclusive scan of the 196 block sums
    int v = (t < NBLK_SCAN) ? g_bsum[t] : 0;
    int x = v;
    #pragma unroll
    for (int o = 1; o < 32; o <<= 1) {
        int y = __shfl_up_sync(0xffffffffu, x, o);
        if (lane >= o) x += y;
    }
    __shared__ int ws[8];
    if (lane == 31) ws[w] = x;
    __syncthreads();
    if (t == 0) {
        int run = 0;
        #pragma unroll
        for (int j = 0; j < 8; j++) { int tmp = ws[j]; ws[j] = run; run += tmp; }
        g_rowptr[N_NODES] = run;
    }
    __syncthreads();
    int excl = x - v + ws[w];
    if (t < NBLK_SCAN) g_bsum[t] = excl;
}

__global__ void k_scan3() {
    int i = blockIdx.x * 256 + threadIdx.x;
    if (i < N_NODES) {
        int r = g_rowptr[i] + g_bsum[blockIdx.x];
        g_rowptr[i] = r;
        g_cursor[i] = r;
    }
}

// ---------------- CSR fill ---------------------------------------------------
__global__ void k_fill(const int* __restrict__ src, const int* __restrict__ dst,
                       const float* __restrict__ ea) {
    for (int i = blockIdx.x * blockDim.x + threadIdx.x; i < TOT_EDGES;
         i += gridDim.x * blockDim.x) {
        if (i < N_EDGES) {
            int d = dst[i];
            int p = atomicAdd(&g_cursor[d], 1);
            g_col[p] = src[i];
            g_eav[p] = ea[i];
        } else {
            int n = i - N_EDGES;
            int p = atomicAdd(&g_cursor[n], 1);
            g_col[p] = n;
            g_eav[p] = g_mean[n / NPG];
        }
    }
}

// ============ split-bf16 mma.sync GEMM + fused attention-logit epilogue ======
static constexpr int MMA_STR  = 80;           // smem row stride bytes (40 bf16)
static constexpr int MMA_MATB = 128 * MMA_STR;
static constexpr int MMA_BUFB = 4 * MMA_MATB; // Ah, Al, Bh, Bl
static constexpr int MMA_SMEM = 2 * MMA_BUFB + 512 + 512 + 1024 + 1024; // 84992

template <int KDIM, int CH>
__device__ __forceinline__ void cvt_store_chunk(char* smem, int bufoff,
                                                const float4* pfa, const float* pfw,
                                                int tid) {
    #pragma unroll
    for (int i = 0; i < 4; i++) {
        int idx = tid + i * 256;
        int row = idx >> 3, kq = idx & 7;
        float4 v = pfa[i];
        __nv_bfloat162 h0, h1, l0, l1;
        h0.x = __float2bfloat16(v.x); h0.y = __float2bfloat16(v.y);
        h1.x = __float2bfloat16(v.z); h1.y = __float2bfloat16(v.w);
        l0.x = __float2bfloat16(v.x - __bfloat162float(h0.x));
        l0.y = __float2bfloat16(v.y - __bfloat162float(h0.y));
        l1.x = __float2bfloat16(v.z - __bfloat162float(h1.x));
        l1.y = __float2bfloat16(v.w - __bfloat162float(h1.y));
        char* p = smem + bufoff + row * MMA_STR + kq * 8;
        *reinterpret_cast<__nv_bfloat162*>(p)     = h0;
        *reinterpret_cast<__nv_bfloat162*>(p + 4) = h1;
        *reinterpret_cast<__nv_bfloat162*>(p + MMA_MATB)     = l0;
        *reinterpret_cast<__nv_bfloat162*>(p + MMA_MATB + 4) = l1;
    }
    #pragma unroll
    for (int i = 0; i < 8; i++) {
        int idx = tid + i * 256;
        int k2 = idx >> 7, n = idx & 127;
        float w0 = pfw[2 * i], w1 = pfw[2 * i + 1];
        __nv_bfloat162 h, l;
        h.x = __float2bfloat16(w0); h.y = __float2bfloat16(w1);
        l.x = __float2bfloat16(w0 - __bfloat162float(h.x));
        l.y = __float2bfloat16(w1 - __bfloat162float(h.y));
        char* p = smem + bufoff + 2 * MMA_MATB + n * MMA_STR + k2 * 4;
        *reinterpret_cast<__nv_bfloat162*>(p)            = h;
        *reinterpret_cast<__nv_bfloat162*>(p + MMA_MATB) = l;
    }
}

template <int KDIM, int CH>
__global__ void __launch_bounds__(256) k_mma(const float* __restrict__ A,
                                             const float* __restrict__ W,
                                             float* __restrict__ xp,
                                             const float* __restrict__ asrc,
                                             const float* __restrict__ adst,
                                             int M) {
    extern __shared__ char smem[];
    constexpr int NW  = 2 * CH;
    constexpr int KCH = KDIM / 32;
    constexpr int SAS  = 2 * MMA_BUFB;
    constexpr int SAD  = SAS + 512;
    constexpr int SALS = SAD + 512;
    constexpr int SALD = SALS + 1024;

    const int tid = threadIdx.x;
    const int wid = tid >> 5, lane = tid & 31;
    const int wm = wid & 3, wn = wid >> 2;
    const int brow = blockIdx.y * 128;
    const int bcol = blockIdx.x * 128;
    const uint32_t sb = smem_to_u32(smem);

    float* s_as  = reinterpret_cast<float*>(smem + SAS);
    float* s_ad  = reinterpret_cast<float*>(smem + SAD);
    float* s_als = reinterpret_cast<float*>(smem + SALS);
    float* s_ald = reinterpret_cast<float*>(smem + SALD);
    if (tid < 128) { s_as[tid] = asrc[bcol + tid]; s_ad[tid] = adst[bcol + tid]; }
    s_als[tid] = 0.f;
    s_ald[tid] = 0.f;

    const uint32_t aoff = (uint32_t)((lane & 15) * MMA_STR + (lane >> 4) * 16);
    const uint32_t boff = (uint32_t)(((lane & 7) + ((lane >> 4) & 1) * 8) * MMA_STR
                                     + ((lane >> 3) & 1) * 16);

    float4 pfa[4];
    float  pfw[16];
    #pragma unroll
    for (int i = 0; i < 4; i++) {
        int idx = tid + i * 256;
        int row = idx >> 3, kq = idx & 7;
        int gr = brow + row;
        pfa[i] = (gr < M) ? *reinterpret_cast<const float4*>(A + (size_t)gr * KDIM + kq * 4)
                          : make_float4(0.f, 0.f, 0.f, 0.f);
    }
    #pragma unroll
    for (int i = 0; i < 8; i++) {
        int idx = tid + i * 256;
        int k = (idx >> 7) * 2, n = idx & 127;
        pfw[2 * i]     = W[(size_t)k * NW + bcol + n];
        pfw[2 * i + 1] = W[(size_t)(k + 1) * NW + bcol + n];
    }
    cvt_store_chunk<KDIM, CH>(smem, 0, pfa, pfw, tid);
    __syncthreads();

    float acc[2][8][4];
    #pragma unroll
    for (int a = 0; a < 2; a++)
        #pragma unroll
        for (int b = 0; b < 8; b++)
            #pragma unroll
            for (int c = 0; c < 4; c++) acc[a][b][c] = 0.f;

    int buf = 0;
    for (int kc = 0; kc < KCH; kc++) {
        if (kc + 1 < KCH) {
            const int kb = (kc + 1) * 32;
            #pragma unroll
            for (int i = 0; i < 4; i++) {
                int idx = tid + i * 256;
                int row = idx >> 3, kq = idx & 7;
                int gr = brow + row;
                pfa[i] = (gr < M)
                    ? *reinterpret_cast<const float4*>(A + (size_t)gr * KDIM + kb + kq * 4)
                    : make_float4(0.f, 0.f, 0.f, 0.f);
            }
            #pragma unroll
            for (int i = 0; i < 8; i++) {
                int idx = tid + i * 256;
                int k = kb + (idx >> 7) * 2, n = idx & 127;
                pfw[2 * i]     = W[(size_t)k * NW + bcol + n];
                pfw[2 * i + 1] = W[(size_t)(k + 1) * NW + bcol + n];
            }
        }
        const uint32_t baseA = sb + buf * MMA_BUFB;
        const uint32_t baseB = baseA + 2 * MMA_MATB;
        #pragma unroll
        for (int ks = 0; ks < 2; ks++) {
            uint32_t ah[2][4], al[2][4], bh[4][4], bl[4][4];
            #pragma unroll
            for (int mf = 0; mf < 2; mf++) {
                uint32_t ad = baseA + (uint32_t)((wm * 32 + mf * 16) * MMA_STR) + ks * 32 + aoff;
                LDSM4(ah[mf], ad);
                LDSM4(al[mf], ad + MMA_MATB);
            }
            #pragma unroll
            for (int np = 0; np < 4; np++) {
                uint32_t bd = baseB + (uint32_t)((wn * 64 + np * 16) * MMA_STR) + ks * 32 + boff;
                LDSM4(bh[np], bd);
                LDSM4(bl[np], bd + MMA_MATB);
            }
            #pragma unroll
            for (int mf = 0; mf < 2; mf++)
                #pragma unroll
                for (int np = 0; np < 4; np++)
                    #pragma unroll
                    for (int hh = 0; hh < 2; hh++) {
                        int nf = np * 2 + hh;
                        MMA_BF16(acc[mf][nf], ah[mf], bh[np][2 * hh], bh[np][2 * hh + 1]);
                        MMA_BF16(acc[mf][nf], al[mf], bh[np][2 * hh], bh[np][2 * hh + 1]);
                        MMA_BF16(acc[mf][nf], ah[mf], bl[np][2 * hh], bl[np][2 * hh + 1]);
                    }
        }
        if (kc + 1 < KCH) {
            cvt_store_chunk<KDIM, CH>(smem, (buf ^ 1) * MMA_BUFB, pfa, pfw, tid);
            __syncthreads();
            buf ^= 1;
        }
    }

    // ---- epilogue: write xp + fused attention logits ----
    #pragma unroll
    for (int mf = 0; mf < 2; mf++)
        #pragma unroll
        for (int r = 0; r < 2; r++) {
            int row_local = wm * 32 + mf * 16 + (lane >> 2) + r * 8;
            int m = brow + row_local;
            float als = 0.f, ald = 0.f;
            #pragma unroll
            for (int nf = 0; nf < 8; nf++) {
                float c0 = acc[mf][nf][r * 2 + 0], c1 = acc[mf][nf][r * 2 + 1];
                int j = wn * 64 + nf * 8 + (lane & 3) * 2;
                als += c0 * s_as[j] + c1 * s_as[j + 1];
                ald += c0 * s_ad[j] + c1 * s_ad[j + 1];
                if (m < M) {
                    int ncol = bcol + j;
                    int head = ncol / CH, c = ncol % CH;
                    *reinterpret_cast<float2*>(xp + ((size_t)m * 2 + head) * CH + c) =
                        make_float2(c0, c1);
                }
            }
            als += __shfl_xor_sync(0xffffffffu, als, 1);
            als += __shfl_xor_sync(0xffffffffu, als, 2);
            ald += __shfl_xor_sync(0xffffffffu, ald, 1);
            ald += __shfl_xor_sync(0xffffffffu, ald, 2);
            if ((lane & 3) == 0) {
                int sidx = (CH == 64 ? wn * 128 : 0) + row_local;
                atomicAdd(&s_als[sidx], als);
                atomicAdd(&s_ald[sidx], ald);
            }
        }
    __syncthreads();
    if (CH == 128) {
        if (tid < 128) {
            int m = brow + tid;
            if (m < M) {
                g_als[2 * m + blockIdx.x] = s_als[tid];
                g_ald[2 * m + blockIdx.x] = s_ald[tid];
            }
        }
    } else {
        int h = tid >> 7, t = tid & 127;
        int m = brow + t;
        if (m < M) {
            g_als[2 * m + h] = s_als[tid];
            g_ald[2 * m + h] = s_ald[tid];
        }
    }
}

// ---------------- warp-per-dst online-softmax aggregation -------------------
// CLS=false: write out[warp*C + c] (h1, with relu).
// CLS=true  (C=64): fuse classifier — out gets pred[n, NC].
template <int C, bool RELU, bool CLS>
__global__ void k_agg(const float* __restrict__ xp, const float* __restrict__ bias,
                      float* __restrict__ out, int keoff,
                      const float* __restrict__ Wc, const float* __restrict__ bc) {
    int warp = (blockIdx.x * blockDim.x + threadIdx.x) >> 5;
    int lane = threadIdx.x & 31;
    if (warp >= N_NODES) return;
    constexpr int V = C / 32;
    float acc0[V], acc1[V];
    #pragma unroll
    for (int j = 0; j < V; j++) { acc0[j] = 0.f; acc1[j] = 0.f; }
    float m0 = -1e30f, m1 = -1e30f, d0 = 0.f, d1 = 0.f;
    float ad0 = g_ald[2 * warp], ad1 = g_ald[2 * warp + 1];
    float ke0 = g_ke[keoff], ke1 = g_ke[keoff + 1];
    int p0 = g_rowptr[warp], p1 = g_rowptr[warp + 1];
    int c0 = lane * V;
    for (int p = p0; p < p1; p++) {
        int s = g_col[p];
        float ea = g_eav[p];
        float a0 = g_als[2 * s]     + ad0 + ea * ke0;
        float a1 = g_als[2 * s + 1] + ad1 + ea * ke1;
        a0 = a0 > 0.f ? a0 : 0.2f * a0;
        a1 = a1 > 0.f ? a1 : 0.2f * a1;
        float nm0 = fmaxf(m0, a0), nm1 = fmaxf(m1, a1);
        float sc0 = __expf(m0 - nm0), sc1 = __expf(m1 - nm1);
        float w0  = __expf(a0 - nm0), w1  = __expf(a1 - nm1);
        d0 = d0 * sc0 + w0;  d1 = d1 * sc1 + w1;
        m0 = nm0;  m1 = nm1;
        const float* row = xp + (size_t)s * 2 * C + c0;
        float v0[V], v1[V];
        if constexpr (V == 4) {
            float4 t0 = *reinterpret_cast<const float4*>(row);
            float4 t1 = *reinterpret_cast<const float4*>(row + C);
            v0[0] = t0.x; v0[1] = t0.y; v0[2] = t0.z; v0[3] = t0.w;
            v1[0] = t1.x; v1[1] = t1.y; v1[2] = t1.z; v1[3] = t1.w;
        } else {
            float2 t0 = *reinterpret_cast<const float2*>(row);
            float2 t1 = *reinterpret_cast<const float2*>(row + C);
            v0[0] = t0.x; v0[1] = t0.y;
            v1[0] = t1.x; v1[1] = t1.y;
        }
        #pragma unroll
        for (int j = 0; j < V; j++) {
            acc0[j] = acc0[j] * sc0 + w0 * v0[j];
            acc1[j] = acc1[j] * sc1 + w1 * v1[j];
        }
    }
    float r0 = 1.f / (d0 + 1e-16f), r1 = 1.f / (d1 + 1e-16f);
    float res[V];
    #pragma unroll
    for (int j = 0; j < V; j++) {
        float vv = 0.5f * (acc0[j] * r0 + acc1[j] * r1) + bias[c0 + j];
        if (RELU) vv = fmaxf(vv, 0.f);
        res[j] = vv;
    }
    if constexpr (!CLS) {
        if constexpr (V == 4)
            *reinterpret_cast<float4*>(&out[(size_t)warp * C + c0]) =
                make_float4(res[0], res[1], res[2], res[3]);
        else
            *reinterpret_cast<float2*>(&out[(size_t)warp * C + c0]) =
                make_float2(res[0], res[1]);
    } else {
        // fused classifier: pred[warp, c] = sum_k h2[k] * Wc[k, c] + bc[c]
        float part[NC];
        #pragma unroll
        for (int c = 0; c < NC; c++) {
            float s = 0.f;
            #pragma unroll
            for (int j = 0; j < V; j++)
                s = fmaf(res[j], __ldg(&Wc[(c0 + j) * NC + c]), s);
            part[c] = s;
        }
        #pragma unroll
        for (int off = 16; off; off >>= 1)
            #pragma unroll
            for (int c = 0; c < NC; c++)
                part[c] += __shfl_xor_sync(0xffffffffu, part[c], off);
        if (lane < NC)
            out[(size_t)warp * NC + lane] = part[lane] + __ldg(&bc[lane]);
    }
}

__global__ void k_y(const int* __restrict__ y, float* __restrict__ out) {
    int i = blockIdx.x * blockDim.x + threadIdx.x;
    if (i < N_NODES) out[i] = (float)y[i];
}

// ---------------- launch ------------------------------------------------------
static void* sym(const void* s) { void* p = nullptr; cudaGetSymbolAddress(&p, s); return p; }

extern "C" void kernel_launch(void* const* d_in, const int* in_sizes, int n_in,
                              void* d_out, int out_size) {
    const float* x    = (const float*)d_in[0];
    const int*   ei   = (const int*)  d_in[1];
    const float* ea   = (const float*)d_in[2];
    const int*   y    = (const int*)  d_in[4];
    const float* W1   = (const float*)d_in[5];
    const float* as1  = (const float*)d_in[6];
    const float* ad1  = (const float*)d_in[7];
    const float* We1  = (const float*)d_in[8];
    const float* ae1  = (const float*)d_in[9];
    const float* b1   = (const float*)d_in[10];
    const float* W2   = (const float*)d_in[11];
    const float* as2  = (const float*)d_in[12];
    const float* ad2  = (const float*)d_in[13];
    const float* We2  = (const float*)d_in[14];
    const float* ae2  = (const float*)d_in[15];
    const float* b2   = (const float*)d_in[16];
    const float* Wc   = (const float*)d_in[17];
    const float* bc   = (const float*)d_in[18];
    float* out = (float*)d_out;
    const int* src = ei;
    const int* dst = ei + N_EDGES;

    float* xp1 = (float*)sym(g_xp1);
    float* h1  = (float*)sym(g_h1);
    float* xp2 = (float*)sym(g_xp2);

    static cudaStream_t s2 = nullptr;
    static cudaEvent_t evFork = nullptr, evJoin = nullptr;
    if (!s2) {
        cudaStreamCreateWithFlags(&s2, cudaStreamNonBlocking);
        cudaEventCreateWithFlags(&evFork, cudaEventDisableTiming);
        cudaEventCreateWithFlags(&evJoin, cudaEventDisableTiming);
    }

    cudaFuncSetAttribute(k_mma<256, 128>,
                         cudaFuncAttributeMaxDynamicSharedMemorySize, MMA_SMEM);
    cudaFuncSetAttribute(k_mma<128, 64>,
                         cudaFuncAttributeMaxDynamicSharedMemorySize, MMA_SMEM);

    const int MB = (N_NODES + 127) / 128;   // 391

    // Fork: CSR build chain + y on s2, concurrent with layer-1 GEMM.
    cudaEventRecord(evFork, 0);
    cudaStreamWaitEvent(s2, evFork, 0);

    k_init<<<(N_NODES + 255) / 256, 256, 0, s2>>>();
    k_edge_pass1<<<512, 256, 0, s2>>>(src, dst, ea);
    k_scan1<<<NBLK_SCAN, 256, 0, s2>>>();
    k_scan2f<<<1, 256, 0, s2>>>(We1, ae1, We2, ae2);
    k_scan3<<<NBLK_SCAN, 256, 0, s2>>>();
    k_fill<<<1024, 256, 0, s2>>>(src, dst, ea);
    if (out_size >= N_NODES * NC + N_NODES)
        k_y<<<(N_NODES + 255) / 256, 256, 0, s2>>>(y, out + (size_t)N_NODES * NC);
    cudaEventRecord(evJoin, s2);

    // Main stream: layer-1 fused GEMM runs concurrently with the CSR build.
    k_mma<256, 128><<<dim3(2, MB), 256, MMA_SMEM>>>(x, W1, xp1, as1, ad1, N_NODES);

    // Join: aggregation needs both xp1/als (main) and CSR (s2).
    cudaStreamWaitEvent(0, evJoin, 0);

    k_agg<128, true, false><<<(N_NODES * 32 + 255) / 256, 256>>>(
        xp1, b1, h1, 0, nullptr, nullptr);

    // Layer 2 + fused classifier
    k_mma<128, 64><<<dim3(1, MB), 256, MMA_SMEM>>>(h1, W2, xp2, as2, ad2, N_NODES);
    k_agg<64, false, true><<<(N_NODES * 32 + 255) / 256, 256>>>(
        xp2, b2, out, 2, Wc, bc);
}

// round 9
// speedup vs baseline: 2.1626x; 1.0845x over previous
#include <cuda_runtime.h>
#include <cuda_bf16.h>
#include <cuda_fp16.h>
#include <stdint.h>

#define N_NODES 50000
#define N_EDGES 500000
#define NPG     6250
#define N_GRAPHS 8
#define TOT_EDGES (N_EDGES + N_NODES)
#define NC 10
#define NBLK_SCAN ((N_NODES + 255) / 256)   // 196

// ===================== mma.sync helpers (sm_80+ ISA) ========================
__device__ __forceinline__ uint32_t smem_to_u32(const void* p) {
    uint32_t a;
    asm("{ .reg .u64 t; cvta.to.shared.u64 t, %1; cvt.u32.u64 %0, t; }" : "=r"(a) : "l"(p));
    return a;
}
#define LDSM4(r, addr) \
    asm volatile("ldmatrix.sync.aligned.m8n8.x4.shared.b16 {%0,%1,%2,%3}, [%4];" \
        : "=r"((r)[0]), "=r"((r)[1]), "=r"((r)[2]), "=r"((r)[3]) : "r"(addr))
#define MMA_BF16(d, a, b0v, b1v) \
    asm volatile("mma.sync.aligned.m16n8k16.row.col.f32.bf16.bf16.f32 " \
        "{%0,%1,%2,%3}, {%4,%5,%6,%7}, {%8,%9}, {%0,%1,%2,%3};" \
        : "+f"((d)[0]), "+f"((d)[1]), "+f"((d)[2]), "+f"((d)[3]) \
        : "r"((a)[0]), "r"((a)[1]), "r"((a)[2]), "r"((a)[3]), "r"(b0v), "r"(b1v))

// ---------------- scratch (static __device__, no allocation) ----------------
__device__ __align__(16) __half g_xp1[(size_t)N_NODES * 256];  // fp16 messages
__device__ __align__(16) float  g_h1 [(size_t)N_NODES * 128];
__device__ __align__(16) __half g_xp2[(size_t)N_NODES * 128];
__device__ float g_als[N_NODES * 2];
__device__ float g_ald[N_NODES * 2];
__device__ int   g_rowptr[N_NODES + 1];
__device__ int   g_cursor[N_NODES];
__device__ __align__(8) int2 g_cole[TOT_EDGES];   // {src, eav bits}
__device__ float g_gsum[N_GRAPHS];
__device__ int   g_gcnt[N_GRAPHS];
__device__ float g_mean[N_GRAPHS];
__device__ float g_ke[4];
__device__ int   g_bsum[NBLK_SCAN];

// ---------------- init ------------------------------------------------------
__global__ void k_init() {
    int i = blockIdx.x * blockDim.x + threadIdx.x;
    if (i < N_NODES) g_cursor[i] = 1;
    if (i < N_GRAPHS) { g_gsum[i] = 0.f; g_gcnt[i] = 0; }
}

// ---------------- edge pass: per-graph attr stats + in-degree hist ----------
__global__ void k_edge_pass1(const int* __restrict__ src, const int* __restrict__ dst,
                             const float* __restrict__ ea) {
    __shared__ float ss[N_GRAPHS];
    __shared__ int   sc[N_GRAPHS];
    if (threadIdx.x < N_GRAPHS) { ss[threadIdx.x] = 0.f; sc[threadIdx.x] = 0; }
    __syncthreads();
    for (int e = blockIdx.x * blockDim.x + threadIdx.x; e < N_EDGES;
         e += gridDim.x * blockDim.x) {
        int s = src[e];
        int d = dst[e];
        int g = s / NPG;
        atomicAdd(&ss[g], ea[e]);
        atomicAdd(&sc[g], 1);
        atomicAdd(&g_cursor[d], 1);
    }
    __syncthreads();
    if (threadIdx.x < N_GRAPHS) {
        atomicAdd(&g_gsum[threadIdx.x], ss[threadIdx.x]);
        atomicAdd(&g_gcnt[threadIdx.x], sc[threadIdx.x]);
    }
}

// ---------------- scan stage 1 -----------------------------------------------
__global__ void k_scan1() {
    int t = threadIdx.x;
    int i = blockIdx.x * 256 + t;
    int v = (i < N_NODES) ? g_cursor[i] : 0;
    int lane = t & 31, w = t >> 5;
    int x = v;
    #pragma unroll
    for (int o = 1; o < 32; o <<= 1) {
        int y = __shfl_up_sync(0xffffffffu, x, o);
        if (lane >= o) x += y;
    }
    __shared__ int ws[8];
    if (lane == 31) ws[w] = x;
    __syncthreads();
    if (t == 0) {
        int run = 0;
        #pragma unroll
        for (int j = 0; j < 8; j++) { int tmp = ws[j]; ws[j] = run; run += tmp; }
        g_bsum[blockIdx.x] = run;
    }
    __syncthreads();
    int excl = x - v + ws[w];
    if (i < N_NODES) g_rowptr[i] = excl;
}

// ---------------- scan stage 2 + finalize (ke scalars, per-graph means) -----
__global__ void k_scan2f(const float* __restrict__ We1, const float* __restrict__ ae1,
                         const float* __restrict__ We2, const float* __restrict__ ae2) {
    int t = threadIdx.x, w = t >> 5, lane = t & 31;
    {
        float v = 0.f;
        if (w == 0)      { for (int c = lane; c < 128; c += 32) v += We1[c]       * ae1[c]; }
        else if (w == 1) { for (int c = lane; c < 128; c += 32) v += We1[128 + c] * ae1[128 + c]; }
        else if (w == 2) { for (int c = lane; c <  64; c += 32) v += We2[c]       * ae2[c]; }
        else if (w == 3) { for (int c = lane; c <  64; c += 32) v += We2[64 + c]  * ae2[64 + c]; }
        #pragma unroll
        for (int off = 16; off; off >>= 1) v += __shfl_xor_sync(0xffffffffu, v, off);
        if (w < 4 && lane == 0) g_ke[w] = v;
        if (w == 4 && lane < N_GRAPHS)
            g_mean[lane] = g_gsum[lane] / (float)g_gcnt[lane];
    }
    int v = (t < NBLK_SCAN) ? g_bsum[t] : 0;
    int x = v;
    #pragma unroll
    for (int o = 1; o < 32; o <<= 1) {
        int y = __shfl_up_sync(0xffffffffu, x, o);
        if (lane >= o) x += y;
    }
    __shared__ int ws[8];
    if (lane == 31) ws[w] = x;
    __syncthreads();
    if (t == 0) {
        int run = 0;
        #pragma unroll
        for (int j = 0; j < 8; j++) { int tmp = ws[j]; ws[j] = run; run += tmp; }
        g_rowptr[N_NODES] = run;
    }
    __syncthreads();
    int excl = x - v + ws[w];
    if (t < NBLK_SCAN) g_bsum[t] = excl;
}

__global__ void k_scan3() {
    int i = blockIdx.x * 256 + threadIdx.x;
    if (i < N_NODES) {
        int r = g_rowptr[i] + g_bsum[blockIdx.x];
        g_rowptr[i] = r;
        g_cursor[i] = r;
    }
}

// ---------------- CSR fill (interleaved col+eav) ------------------------------
__global__ void k_fill(const int* __restrict__ src, const int* __restrict__ dst,
                       const float* __restrict__ ea) {
    for (int i = blockIdx.x * blockDim.x + threadIdx.x; i < TOT_EDGES;
         i += gridDim.x * blockDim.x) {
        if (i < N_EDGES) {
            int d = dst[i];
            int p = atomicAdd(&g_cursor[d], 1);
            g_cole[p] = make_int2(src[i], __float_as_int(ea[i]));
        } else {
            int n = i - N_EDGES;
            int p = atomicAdd(&g_cursor[n], 1);
            g_cole[p] = make_int2(n, __float_as_int(g_mean[n / NPG]));
        }
    }
}

// ============ split-bf16 mma.sync GEMM + fused attention-logit epilogue ======
static constexpr int MMA_STR  = 80;           // smem row stride bytes (40 bf16)
static constexpr int MMA_MATB = 128 * MMA_STR;
static constexpr int MMA_BUFB = 4 * MMA_MATB; // Ah, Al, Bh, Bl
static constexpr int MMA_SMEM = 2 * MMA_BUFB + 512 + 512 + 1024 + 1024; // 84992

template <int KDIM, int CH>
__device__ __forceinline__ void cvt_store_chunk(char* smem, int bufoff,
                                                const float4* pfa, const float* pfw,
                                                int tid) {
    #pragma unroll
    for (int i = 0; i < 4; i++) {
        int idx = tid + i * 256;
        int row = idx >> 3, kq = idx & 7;
        float4 v = pfa[i];
        __nv_bfloat162 h0, h1, l0, l1;
        h0.x = __float2bfloat16(v.x); h0.y = __float2bfloat16(v.y);
        h1.x = __float2bfloat16(v.z); h1.y = __float2bfloat16(v.w);
        l0.x = __float2bfloat16(v.x - __bfloat162float(h0.x));
        l0.y = __float2bfloat16(v.y - __bfloat162float(h0.y));
        l1.x = __float2bfloat16(v.z - __bfloat162float(h1.x));
        l1.y = __float2bfloat16(v.w - __bfloat162float(h1.y));
        char* p = smem + bufoff + row * MMA_STR + kq * 8;
        *reinterpret_cast<__nv_bfloat162*>(p)     = h0;
        *reinterpret_cast<__nv_bfloat162*>(p + 4) = h1;
        *reinterpret_cast<__nv_bfloat162*>(p + MMA_MATB)     = l0;
        *reinterpret_cast<__nv_bfloat162*>(p + MMA_MATB + 4) = l1;
    }
    #pragma unroll
    for (int i = 0; i < 8; i++) {
        int idx = tid + i * 256;
        int k2 = idx >> 7, n = idx & 127;
        float w0 = pfw[2 * i], w1 = pfw[2 * i + 1];
        __nv_bfloat162 h, l;
        h.x = __float2bfloat16(w0); h.y = __float2bfloat16(w1);
        l.x = __float2bfloat16(w0 - __bfloat162float(h.x));
        l.y = __float2bfloat16(w1 - __bfloat162float(h.y));
        char* p = smem + bufoff + 2 * MMA_MATB + n * MMA_STR + k2 * 4;
        *reinterpret_cast<__nv_bfloat162*>(p)            = h;
        *reinterpret_cast<__nv_bfloat162*>(p + MMA_MATB) = l;
    }
}

template <int KDIM, int CH>
__global__ void __launch_bounds__(256) k_mma(const float* __restrict__ A,
                                             const float* __restrict__ W,
                                             __half* __restrict__ xp,
                                             const float* __restrict__ asrc,
                                             const float* __restrict__ adst,
                                             int M) {
    extern __shared__ char smem[];
    constexpr int NW  = 2 * CH;
    constexpr int KCH = KDIM / 32;
    constexpr int SAS  = 2 * MMA_BUFB;
    constexpr int SAD  = SAS + 512;
    constexpr int SALS = SAD + 512;
    constexpr int SALD = SALS + 1024;

    const int tid = threadIdx.x;
    const int wid = tid >> 5, lane = tid & 31;
    const int wm = wid & 3, wn = wid >> 2;
    const int brow = blockIdx.y * 128;
    const int bcol = blockIdx.x * 128;
    const uint32_t sb = smem_to_u32(smem);

    float* s_as  = reinterpret_cast<float*>(smem + SAS);
    float* s_ad  = reinterpret_cast<float*>(smem + SAD);
    float* s_als = reinterpret_cast<float*>(smem + SALS);
    float* s_ald = reinterpret_cast<float*>(smem + SALD);
    if (tid < 128) { s_as[tid] = asrc[bcol + tid]; s_ad[tid] = adst[bcol + tid]; }
    s_als[tid] = 0.f;
    s_ald[tid] = 0.f;

    const uint32_t aoff = (uint32_t)((lane & 15) * MMA_STR + (lane >> 4) * 16);
    const uint32_t boff = (uint32_t)(((lane & 7) + ((lane >> 4) & 1) * 8) * MMA_STR
                                     + ((lane >> 3) & 1) * 16);

    float4 pfa[4];
    float  pfw[16];
    #pragma unroll
    for (int i = 0; i < 4; i++) {
        int idx = tid + i * 256;
        int row = idx >> 3, kq = idx & 7;
        int gr = brow + row;
        pfa[i] = (gr < M) ? *reinterpret_cast<const float4*>(A + (size_t)gr * KDIM + kq * 4)
                          : make_float4(0.f, 0.f, 0.f, 0.f);
    }
    #pragma unroll
    for (int i = 0; i < 8; i++) {
        int idx = tid + i * 256;
        int k = (idx >> 7) * 2, n = idx & 127;
        pfw[2 * i]     = W[(size_t)k * NW + bcol + n];
        pfw[2 * i + 1] = W[(size_t)(k + 1) * NW + bcol + n];
    }
    cvt_store_chunk<KDIM, CH>(smem, 0, pfa, pfw, tid);
    __syncthreads();

    float acc[2][8][4];
    #pragma unroll
    for (int a = 0; a < 2; a++)
        #pragma unroll
        for (int b = 0; b < 8; b++)
            #pragma unroll
            for (int c = 0; c < 4; c++) acc[a][b][c] = 0.f;

    int buf = 0;
    for (int kc = 0; kc < KCH; kc++) {
        if (kc + 1 < KCH) {
            const int kb = (kc + 1) * 32;
            #pragma unroll
            for (int i = 0; i < 4; i++) {
                int idx = tid + i * 256;
                int row = idx >> 3, kq = idx & 7;
                int gr = brow + row;
                pfa[i] = (gr < M)
                    ? *reinterpret_cast<const float4*>(A + (size_t)gr * KDIM + kb + kq * 4)
                    : make_float4(0.f, 0.f, 0.f, 0.f);
            }
            #pragma unroll
            for (int i = 0; i < 8; i++) {
                int idx = tid + i * 256;
                int k = kb + (idx >> 7) * 2, n = idx & 127;
                pfw[2 * i]     = W[(size_t)k * NW + bcol + n];
                pfw[2 * i + 1] = W[(size_t)(k + 1) * NW + bcol + n];
            }
        }
        const uint32_t baseA = sb + buf * MMA_BUFB;
        const uint32_t baseB = baseA + 2 * MMA_MATB;
        #pragma unroll
        for (int ks = 0; ks < 2; ks++) {
            uint32_t ah[2][4], al[2][4], bh[4][4], bl[4][4];
            #pragma unroll
            for (int mf = 0; mf < 2; mf++) {
                uint32_t ad = baseA + (uint32_t)((wm * 32 + mf * 16) * MMA_STR) + ks * 32 + aoff;
                LDSM4(ah[mf], ad);
                LDSM4(al[mf], ad + MMA_MATB);
            }
            #pragma unroll
            for (int np = 0; np < 4; np++) {
                uint32_t bd = baseB + (uint32_t)((wn * 64 + np * 16) * MMA_STR) + ks * 32 + boff;
                LDSM4(bh[np], bd);
                LDSM4(bl[np], bd + MMA_MATB);
            }
            #pragma unroll
            for (int mf = 0; mf < 2; mf++)
                #pragma unroll
                for (int np = 0; np < 4; np++)
                    #pragma unroll
                    for (int hh = 0; hh < 2; hh++) {
                        int nf = np * 2 + hh;
                        MMA_BF16(acc[mf][nf], ah[mf], bh[np][2 * hh], bh[np][2 * hh + 1]);
                        MMA_BF16(acc[mf][nf], al[mf], bh[np][2 * hh], bh[np][2 * hh + 1]);
                        MMA_BF16(acc[mf][nf], ah[mf], bl[np][2 * hh], bl[np][2 * hh + 1]);
                    }
        }
        if (kc + 1 < KCH) {
            cvt_store_chunk<KDIM, CH>(smem, (buf ^ 1) * MMA_BUFB, pfa, pfw, tid);
            __syncthreads();
            buf ^= 1;
        }
    }

    // ---- epilogue: write xp (fp16) + fused attention logits (fp32) ----
    #pragma unroll
    for (int mf = 0; mf < 2; mf++)
        #pragma unroll
        for (int r = 0; r < 2; r++) {
            int row_local = wm * 32 + mf * 16 + (lane >> 2) + r * 8;
            int m = brow + row_local;
            float als = 0.f, ald = 0.f;
            #pragma unroll
            for (int nf = 0; nf < 8; nf++) {
                float c0 = acc[mf][nf][r * 2 + 0], c1 = acc[mf][nf][r * 2 + 1];
                int j = wn * 64 + nf * 8 + (lane & 3) * 2;
                als += c0 * s_as[j] + c1 * s_as[j + 1];
                ald += c0 * s_ad[j] + c1 * s_ad[j + 1];
                if (m < M) {
                    int ncol = bcol + j;
                    int head = ncol / CH, c = ncol % CH;
                    *reinterpret_cast<__half2*>(xp + ((size_t)m * 2 + head) * CH + c) =
                        __floats2half2_rn(c0, c1);
                }
            }
            als += __shfl_xor_sync(0xffffffffu, als, 1);
            als += __shfl_xor_sync(0xffffffffu, als, 2);
            ald += __shfl_xor_sync(0xffffffffu, ald, 1);
            ald += __shfl_xor_sync(0xffffffffu, ald, 2);
            if ((lane & 3) == 0) {
                int sidx = (CH == 64 ? wn * 128 : 0) + row_local;
                atomicAdd(&s_als[sidx], als);
                atomicAdd(&s_ald[sidx], ald);
            }
        }
    __syncthreads();
    if (CH == 128) {
        if (tid < 128) {
            int m = brow + tid;
            if (m < M) {
                g_als[2 * m + blockIdx.x] = s_als[tid];
                g_ald[2 * m + blockIdx.x] = s_ald[tid];
            }
        }
    } else {
        int h = tid >> 7, t = tid & 127;
        int m = brow + t;
        if (m < M) {
            g_als[2 * m + h] = s_als[tid];
            g_ald[2 * m + h] = s_ald[tid];
        }
    }
}

// ---------------- warp-per-dst online-softmax aggregation (fp16 gathers) -----
template <int C>
__device__ __forceinline__ void ld_row(const __half* row, float* v0, float* v1) {
    constexpr int V = C / 32;
    if constexpr (V == 4) {
        uint2 u0 = *reinterpret_cast<const uint2*>(row);
        uint2 u1 = *reinterpret_cast<const uint2*>(row + C);
        float2 a = __half22float2(*reinterpret_cast<__half2*>(&u0.x));
        float2 b = __half22float2(*reinterpret_cast<__half2*>(&u0.y));
        v0[0] = a.x; v0[1] = a.y; v0[2] = b.x; v0[3] = b.y;
        a = __half22float2(*reinterpret_cast<__half2*>(&u1.x));
        b = __half22float2(*reinterpret_cast<__half2*>(&u1.y));
        v1[0] = a.x; v1[1] = a.y; v1[2] = b.x; v1[3] = b.y;
    } else {
        float2 a = __half22float2(*reinterpret_cast<const __half2*>(row));
        float2 b = __half22float2(*reinterpret_cast<const __half2*>(row + C));
        v0[0] = a.x; v0[1] = a.y;
        v1[0] = b.x; v1[1] = b.y;
    }
}

template <int C, bool RELU, bool CLS>
__global__ void k_agg(const __half* __restrict__ xp, const float* __restrict__ bias,
                      float* __restrict__ out, int keoff,
                      const float* __restrict__ Wc, const float* __restrict__ bc) {
    int warp = (blockIdx.x * blockDim.x + threadIdx.x) >> 5;
    int lane = threadIdx.x & 31;
    if (warp >= N_NODES) return;
    constexpr int V = C / 32;
    float acc0[V], acc1[V];
    #pragma unroll
    for (int j = 0; j < V; j++) { acc0[j] = 0.f; acc1[j] = 0.f; }
    float m0 = -1e30f, m1 = -1e30f, d0 = 0.f, d1 = 0.f;
    float ad0 = g_ald[2 * warp], ad1 = g_ald[2 * warp + 1];
    float ke0 = g_ke[keoff], ke1 = g_ke[keoff + 1];
    int p0 = g_rowptr[warp], p1 = g_rowptr[warp + 1];
    int c0 = lane * V;

    int p = p0;
    for (; p + 1 < p1; p += 2) {
        int2 ceA = g_cole[p], ceB = g_cole[p + 1];
        int sA = ceA.x, sB = ceB.x;
        float eaA = __int_as_float(ceA.y), eaB = __int_as_float(ceB.y);
        float vA0[V], vA1[V], vB0[V], vB1[V];
        ld_row<C>(xp + (size_t)sA * 2 * C + c0, vA0, vA1);
        ld_row<C>(xp + (size_t)sB * 2 * C + c0, vB0, vB1);
        float aA0 = g_als[2 * sA]     + ad0 + eaA * ke0;
        float aA1 = g_als[2 * sA + 1] + ad1 + eaA * ke1;
        float aB0 = g_als[2 * sB]     + ad0 + eaB * ke0;
        float aB1 = g_als[2 * sB + 1] + ad1 + eaB * ke1;
        aA0 = aA0 > 0.f ? aA0 : 0.2f * aA0;
        aA1 = aA1 > 0.f ? aA1 : 0.2f * aA1;
        aB0 = aB0 > 0.f ? aB0 : 0.2f * aB0;
        aB1 = aB1 > 0.f ? aB1 : 0.2f * aB1;
        float nm0 = fmaxf(m0, fmaxf(aA0, aB0));
        float nm1 = fmaxf(m1, fmaxf(aA1, aB1));
        float sc0 = __expf(m0 - nm0), sc1 = __expf(m1 - nm1);
        float wA0 = __expf(aA0 - nm0), wB0 = __expf(aB0 - nm0);
        float wA1 = __expf(aA1 - nm1), wB1 = __expf(aB1 - nm1);
        d0 = d0 * sc0 + wA0 + wB0;
        d1 = d1 * sc1 + wA1 + wB1;
        m0 = nm0;  m1 = nm1;
        #pragma unroll
        for (int j = 0; j < V; j++) {
            acc0[j] = fmaf(acc0[j], sc0, fmaf(wA0, vA0[j], wB0 * vB0[j]));
            acc1[j] = fmaf(acc1[j], sc1, fmaf(wA1, vA1[j], wB1 * vB1[j]));
        }
    }
    if (p < p1) {
        int2 ce = g_cole[p];
        int s = ce.x;
        float ea = __int_as_float(ce.y);
        float v0[V], v1[V];
        ld_row<C>(xp + (size_t)s * 2 * C + c0, v0, v1);
        float a0 = g_als[2 * s]     + ad0 + ea * ke0;
        float a1 = g_als[2 * s + 1] + ad1 + ea * ke1;
        a0 = a0 > 0.f ? a0 : 0.2f * a0;
        a1 = a1 > 0.f ? a1 : 0.2f * a1;
        float nm0 = fmaxf(m0, a0), nm1 = fmaxf(m1, a1);
        float sc0 = __expf(m0 - nm0), sc1 = __expf(m1 - nm1);
        float w0  = __expf(a0 - nm0), w1  = __expf(a1 - nm1);
        d0 = d0 * sc0 + w0;  d1 = d1 * sc1 + w1;
        #pragma unroll
        for (int j = 0; j < V; j++) {
            acc0[j] = fmaf(acc0[j], sc0, w0 * v0[j]);
            acc1[j] = fmaf(acc1[j], sc1, w1 * v1[j]);
        }
    }

    float r0 = 1.f / (d0 + 1e-16f), r1 = 1.f / (d1 + 1e-16f);
    float res[V];
    #pragma unroll
    for (int j = 0; j < V; j++) {
        float vv = 0.5f * (acc0[j] * r0 + acc1[j] * r1) + bias[c0 + j];
        if (RELU) vv = fmaxf(vv, 0.f);
        res[j] = vv;
    }
    if constexpr (!CLS) {
        if constexpr (V == 4)
            *reinterpret_cast<float4*>(&out[(size_t)warp * C + c0]) =
                make_float4(res[0], res[1], res[2], res[3]);
        else
            *reinterpret_cast<float2*>(&out[(size_t)warp * C + c0]) =
                make_float2(res[0], res[1]);
    } else {
        float part[NC];
        #pragma unroll
        for (int c = 0; c < NC; c++) {
            float s = 0.f;
            #pragma unroll
            for (int j = 0; j < V; j++)
                s = fmaf(res[j], __ldg(&Wc[(c0 + j) * NC + c]), s);
            part[c] = s;
        }
        #pragma unroll
        for (int off = 16; off; off >>= 1)
            #pragma unroll
            for (int c = 0; c < NC; c++)
                part[c] += __shfl_xor_sync(0xffffffffu, part[c], off);
        if (lane < NC)
            out[(size_t)warp * NC + lane] = part[lane] + __ldg(&bc[lane]);
    }
}

__global__ void k_y(const int* __restrict__ y, float* __restrict__ out) {
    int i = blockIdx.x * blockDim.x + threadIdx.x;
    if (i < N_NODES) out[i] = (float)y[i];
}

// ---------------- launch ------------------------------------------------------
static void* sym(const void* s) { void* p = nullptr; cudaGetSymbolAddress(&p, s); return p; }

extern "C" void kernel_launch(void* const* d_in, const int* in_sizes, int n_in,
                              void* d_out, int out_size) {
    const float* x    = (const float*)d_in[0];
    const int*   ei   = (const int*)  d_in[1];
    const float* ea   = (const float*)d_in[2];
    const int*   y    = (const int*)  d_in[4];
    const float* W1   = (const float*)d_in[5];
    const float* as1  = (const float*)d_in[6];
    const float* ad1  = (const float*)d_in[7];
    const float* We1  = (const float*)d_in[8];
    const float* ae1  = (const float*)d_in[9];
    const float* b1   = (const float*)d_in[10];
    const float* W2   = (const float*)d_in[11];
    const float* as2  = (const float*)d_in[12];
    const float* ad2  = (const float*)d_in[13];
    const float* We2  = (const float*)d_in[14];
    const float* ae2  = (const float*)d_in[15];
    const float* b2   = (const float*)d_in[16];
    const float* Wc   = (const float*)d_in[17];
    const float* bc   = (const float*)d_in[18];
    float* out = (float*)d_out;
    const int* src = ei;
    const int* dst = ei + N_EDGES;

    __half* xp1 = (__half*)sym(g_xp1);
    float*  h1  = (float*) sym(g_h1);
    __half* xp2 = (__half*)sym(g_xp2);

    static cudaStream_t s2 = nullptr;
    static cudaEvent_t evFork = nullptr, evJoin = nullptr;
    if (!s2) {
        cudaStreamCreateWithFlags(&s2, cudaStreamNonBlocking);
        cudaEventCreateWithFlags(&evFork, cudaEventDisableTiming);
        cudaEventCreateWithFlags(&evJoin, cudaEventDisableTiming);
    }

    cudaFuncSetAttribute(k_mma<256, 128>,
                         cudaFuncAttributeMaxDynamicSharedMemorySize, MMA_SMEM);
    cudaFuncSetAttribute(k_mma<128, 64>,
                         cudaFuncAttributeMaxDynamicSharedMemorySize, MMA_SMEM);

    const int MB = (N_NODES + 127) / 128;   // 391

    // Fork: CSR build chain + y on s2, concurrent with layer-1 GEMM.
    cudaEventRecord(evFork, 0);
    cudaStreamWaitEvent(s2, evFork, 0);

    k_init<<<(N_NODES + 255) / 256, 256, 0, s2>>>();
    k_edge_pass1<<<512, 256, 0, s2>>>(src, dst, ea);
    k_scan1<<<NBLK_SCAN, 256, 0, s2>>>();
    k_scan2f<<<1, 256, 0, s2>>>(We1, ae1, We2, ae2);
    k_scan3<<<NBLK_SCAN, 256, 0, s2>>>();
    k_fill<<<1024, 256, 0, s2>>>(src, dst, ea);
    if (out_size >= N_NODES * NC + N_NODES)
        k_y<<<(N_NODES + 255) / 256, 256, 0, s2>>>(y, out + (size_t)N_NODES * NC);
    cudaEventRecord(evJoin, s2);

    // Main stream: layer-1 fused GEMM runs concurrently with the CSR build.
    k_mma<256, 128><<<dim3(2, MB), 256, MMA_SMEM>>>(x, W1, xp1, as1, ad1, N_NODES);

    // Join: aggregation needs both xp1/als (main) and CSR (s2).
    cudaStreamWaitEvent(0, evJoin, 0);

    k_agg<128, true, false><<<(N_NODES * 32 + 255) / 256, 256>>>(
        xp1, b1, h1, 0, nullptr, nullptr);

    // Layer 2 + fused classifier
    k_mma<128, 64><<<dim3(1, MB), 256, MMA_SMEM>>>(h1, W2, xp2, as2, ad2, N_NODES);
    k_agg<64, false, true><<<(N_NODES * 32 + 255) / 256, 256>>>(
        xp2, b2, out, 2, Wc, bc);
}